// round 14
// baseline (speedup 1.0000x reference)
#include <cuda_runtime.h>
#include <cuda_fp16.h>
#include <cstdint>
#include <math.h>

#define NN   50000
#define CC   256
#define HH   8
#define HDIM 32
#define MM   800000
#define HIDN 1024
#define QK_SCALE 0.17677669529663687f
#define LN_EPS 1e-5f

// ---------------- scratch (static device globals; no allocation) -------------
__device__ __align__(16) float g_q  [NN * CC];            // scaled q (fp32)
__device__ __align__(16) __half g_kv[NN * HH * 64];       // [n][h][k32|v32] fp16
__device__ __align__(16) float g_f2 [NN * CC];
__device__ __align__(16) __half g_xn_h[NN * CC],  g_xn_l[NN * CC];
__device__ __align__(16) __half g_at_h[NN * CC];
__device__ __align__(16) __half g_y_h [NN * CC];
__device__ __align__(16) __half g_h1_h[NN * HIDN];
__device__ __align__(16) __half g_wqkv[3*CC*CC];
__device__ __align__(16) __half g_wprj[CC*CC];
__device__ __align__(16) __half g_wfc1[HIDN*CC];
__device__ __align__(16) __half g_wfc2[CC*HIDN];
__device__ int g_cnt[NN];
__device__ int g_rowptr[NN + 1];
__device__ int g_cursor[NN];
__device__ int g_bsums[128];
__device__ int g_nbr[MM];

// ---------------- common PTX helpers ------------------------------------------
__device__ __forceinline__ uint32_t smem_u32(const void* p) {
    uint32_t a;
    asm("{ .reg .u64 t; cvta.to.shared.u64 t, %1; cvt.u32.u64 %0, t; }" : "=r"(a) : "l"(p));
    return a;
}

__device__ __forceinline__ void cp16(uint32_t dst, const void* src) {
    asm volatile("cp.async.cg.shared.global [%0],[%1],16;\n" :: "r"(dst), "l"(src));
}
#define CP_COMMIT() asm volatile("cp.async.commit_group;\n")
#define CP_WAIT(n)  asm volatile("cp.async.wait_group %0;\n" :: "n"(n))

// ---------------- fp32 -> fp16 weight round ----------------------------------
__global__ void round_kernel(const float* __restrict__ w,
                             __half* __restrict__ wh, int n)
{
    int i = blockIdx.x * blockDim.x + threadIdx.x;
    if (i < n) wh[i] = __float2half_rn(w[i]);
}

// ---------------- CSR build --------------------------------------------------
__global__ void zero_cnt_kernel() {
    int i = blockIdx.x * blockDim.x + threadIdx.x;
    if (i < NN) g_cnt[i] = 0;
}

__global__ void count_kernel(const int* __restrict__ ei) {
    int e = blockIdx.x * blockDim.x + threadIdx.x;
    if (e < MM) atomicAdd(&g_cnt[ei[e]], 1);
}

#define SCAN_B 512
__global__ void scan1_kernel() {
    __shared__ int sh[SCAN_B];
    int tid = threadIdx.x;
    int i = blockIdx.x * SCAN_B + tid;
    int v = (i < NN) ? g_cnt[i] : 0;
    sh[tid] = v;
    __syncthreads();
    for (int off = 1; off < SCAN_B; off <<= 1) {
        int t = (tid >= off) ? sh[tid - off] : 0;
        __syncthreads();
        sh[tid] += t;
        __syncthreads();
    }
    if (i < NN) g_rowptr[i] = sh[tid] - v;
    if (tid == SCAN_B - 1) g_bsums[blockIdx.x] = sh[tid];
}

__global__ void scan2_kernel(int nb) {
    __shared__ int sh[128];
    int tid = threadIdx.x;
    int v = (tid < nb) ? g_bsums[tid] : 0;
    sh[tid] = v;
    __syncthreads();
    for (int off = 1; off < 128; off <<= 1) {
        int t = (tid >= off) ? sh[tid - off] : 0;
        __syncthreads();
        sh[tid] += t;
        __syncthreads();
    }
    if (tid < nb) g_bsums[tid] = sh[tid] - v;   // exclusive
}

__global__ void scan3_kernel() {
    int i = blockIdx.x * SCAN_B + threadIdx.x;
    if (i < NN) {
        int v = g_rowptr[i] + g_bsums[blockIdx.x];
        g_rowptr[i] = v;
        g_cursor[i] = v;
    }
    if (i == 0) g_rowptr[NN] = MM;
}

__global__ void scatter_kernel(const int* __restrict__ ei) {
    int e = blockIdx.x * blockDim.x + threadIdx.x;
    if (e < MM) {
        int n = ei[e];
        int p = atomicAdd(&g_cursor[n], 1);
        g_nbr[p] = ei[MM + e];
    }
}

// ---------------- LayerNorm -> fp16 (optionally split) ------------------------
__global__ void ln_split_kernel(const float* __restrict__ x, const float* __restrict__ g,
                                const float* __restrict__ b,
                                __half* __restrict__ yh, __half* __restrict__ yl)
{
    int row  = blockIdx.x * 8 + (threadIdx.x >> 5);
    int lane = threadIdx.x & 31;
    if (row >= NN) return;
    const float4* xr = (const float4*)(x + (size_t)row * CC);
    float4 a = xr[lane];
    float4 c = xr[lane + 32];
    float s = a.x + a.y + a.z + a.w + c.x + c.y + c.z + c.w;
    float q = a.x*a.x + a.y*a.y + a.z*a.z + a.w*a.w
            + c.x*c.x + c.y*c.y + c.z*c.z + c.w*c.w;
    #pragma unroll
    for (int o = 16; o; o >>= 1) {
        s += __shfl_xor_sync(0xffffffffu, s, o);
        q += __shfl_xor_sync(0xffffffffu, q, o);
    }
    float mean = s * (1.0f / CC);
    float var  = q * (1.0f / CC) - mean * mean;
    float rstd = rsqrtf(var + LN_EPS);
    const float4* gv = (const float4*)g;
    const float4* bv = (const float4*)b;
    float4 g1 = gv[lane], g2 = gv[lane + 32];
    float4 b1 = bv[lane], b2 = bv[lane + 32];
    float o1[4], o2[4];
    o1[0] = (a.x - mean) * rstd * g1.x + b1.x;
    o1[1] = (a.y - mean) * rstd * g1.y + b1.y;
    o1[2] = (a.z - mean) * rstd * g1.z + b1.z;
    o1[3] = (a.w - mean) * rstd * g1.w + b1.w;
    o2[0] = (c.x - mean) * rstd * g2.x + b2.x;
    o2[1] = (c.y - mean) * rstd * g2.y + b2.y;
    o2[2] = (c.z - mean) * rstd * g2.z + b2.z;
    o2[3] = (c.w - mean) * rstd * g2.w + b2.w;

    __half h1[4], h2[4];
    #pragma unroll
    for (int i = 0; i < 4; i++) {
        h1[i] = __float2half_rn(o1[i]);
        h2[i] = __float2half_rn(o2[i]);
    }
    size_t base = (size_t)row * CC;
    *(uint2*)&yh[base + lane * 4]       = *(uint2*)h1;
    *(uint2*)&yh[base + 128 + lane * 4] = *(uint2*)h2;
    if (yl) {
        __half l1[4], l2[4];
        #pragma unroll
        for (int i = 0; i < 4; i++) {
            l1[i] = __float2half_rn(o1[i] - __half2float(h1[i]));
            l2[i] = __float2half_rn(o2[i] - __half2float(h2[i]));
        }
        *(uint2*)&yl[base + lane * 4]       = *(uint2*)l1;
        *(uint2*)&yl[base + 128 + lane * 4] = *(uint2*)l2;
    }
}

// ---------------- fp16 compensated GEMM, 3-stage cp.async pipeline ------------
#define BM 128
#define BN 128
#define BK 32
#define BKP 40
#define TILE (BM * BKP)
#define ARRB (TILE * 2)
#define STAGEB (3 * ARRB)          // 30720 B per stage (Ah, Al, Bh)
#define NSTG 3

#define EPI_QKV  0
#define EPI_GELU 1
#define EPI_RES  2

__device__ __forceinline__ void ldsm4(unsigned& r0, unsigned& r1, unsigned& r2,
                                      unsigned& r3, uint32_t addr)
{
    asm volatile("ldmatrix.sync.aligned.m8n8.x4.shared.b16 {%0,%1,%2,%3}, [%4];"
                 : "=r"(r0), "=r"(r1), "=r"(r2), "=r"(r3) : "r"(addr));
}

__device__ __forceinline__ void mma_f16(float4& d,
    unsigned a0, unsigned a1, unsigned a2, unsigned a3,
    unsigned b0, unsigned b1)
{
    asm volatile(
        "mma.sync.aligned.m16n8k16.row.col.f32.f16.f16.f32 "
        "{%0,%1,%2,%3},{%4,%5,%6,%7},{%8,%9},{%0,%1,%2,%3};"
        : "+f"(d.x), "+f"(d.y), "+f"(d.z), "+f"(d.w)
        : "r"(a0), "r"(a1), "r"(a2), "r"(a3), "r"(b0), "r"(b1));
}

// fast exact-enough gelu: x*sigmoid(1.59576912*x*(1+0.044715*x^2))
__device__ __forceinline__ float fast_gelu(float x) {
    float w = 1.59576912f * x * (1.0f + 0.044715f * x * x);
    return __fdividef(x, 1.0f + __expf(-w));
}

// two_term: 1 = always, 0 = never, -1 = auto (q columns only, for EPI_QKV)
__global__ __launch_bounds__(256, 2)
void gemm_sp_kernel(const __half* __restrict__ Ah, const __half* __restrict__ Al,
                    const __half* __restrict__ Bh,
                    const float* __restrict__ bias, const float* __restrict__ resid,
                    float* __restrict__ Cf, __half* __restrict__ Ch,
                    int M, int Nn, int Kk, int epi, int two_term)
{
    extern __shared__ __half smem[];
    const uint32_t sb0 = smem_u32(smem);

    const int tid  = threadIdx.x;
    const int row0 = blockIdx.y * BM;
    const int col0 = blockIdx.x * BN;
    const int tt   = (two_term >= 0) ? two_term : ((col0 >> 8) == 0 ? 1 : 0);
    const int warp   = tid >> 5;
    const int lane   = tid & 31;
    const int warp_m = warp >> 2;
    const int warp_n = warp & 3;
    const int g = lane >> 2;
    const int t = lane & 3;

    const int rowA = warp_m * 64 + (lane & 15);
    const int colA = 8 * (lane >> 4);
    const uint32_t offA = (uint32_t)(rowA * BKP + colA) * 2;
    const int rowB = warp_n * 32 + (lane & 7) + 8 * ((lane >> 4) & 1);
    const int colB = 8 * ((lane >> 3) & 1);
    const uint32_t offB = (uint32_t)(rowB * BKP + colB) * 2;

    const int ch0 = tid * 2;
    const int nKiter = Kk / BK;

    float4 acc[4][4];
    #pragma unroll
    for (int i = 0; i < 4; i++)
        #pragma unroll
        for (int j = 0; j < 4; j++) acc[i][j] = make_float4(0.f, 0.f, 0.f, 0.f);

    auto stage = [&](int st, int k0) {
        uint32_t base = sb0 + st * STAGEB;
        #pragma unroll
        for (int q = 0; q < 2; q++) {
            int idx = ch0 + q;
            int r    = idx >> 2;
            int c16  = idx & 3;
            int ar = row0 + r; if (ar >= M) ar = M - 1;
            size_t aoff = (size_t)ar * Kk + k0 + c16 * 8;
            int br = col0 + r;
            size_t boff = (size_t)br * Kk + k0 + c16 * 8;
            uint32_t d = (uint32_t)(r * BKP + c16 * 8) * 2;
            cp16(base + 0 * ARRB + d, Ah + aoff);
            if (tt) cp16(base + 1 * ARRB + d, Al + aoff);
            cp16(base + 2 * ARRB + d, Bh + boff);
        }
        CP_COMMIT();
    };

    stage(0, 0);
    stage(1, BK);

    for (int it = 0; it < nKiter; it++) {
        if (it + 1 < nKiter) { CP_WAIT(1); } else { CP_WAIT(0); }
        __syncthreads();                       // single barrier per iter

        const uint32_t base = sb0 + (it % NSTG) * STAGEB;
        const uint32_t aAh = base + offA;
        const uint32_t aAl = base + ARRB + offA;
        const uint32_t aBh = base + 2 * ARRB + offB;

        #pragma unroll
        for (int s = 0; s < 2; s++) {
            unsigned bh[4][2];
            ldsm4(bh[0][0], bh[0][1], bh[1][0], bh[1][1], aBh + s * 32);
            ldsm4(bh[2][0], bh[2][1], bh[3][0], bh[3][1], aBh + 16 * BKP * 2 + s * 32);
            #pragma unroll
            for (int mi = 0; mi < 4; mi++) {
                unsigned ah0, ah1, ah2, ah3;
                ldsm4(ah0, ah1, ah2, ah3, aAh + mi * (16 * BKP * 2) + s * 32);
                #pragma unroll
                for (int ni = 0; ni < 4; ni++)
                    mma_f16(acc[mi][ni], ah0, ah1, ah2, ah3, bh[ni][0], bh[ni][1]);
                if (tt) {
                    unsigned al0, al1, al2, al3;
                    ldsm4(al0, al1, al2, al3, aAl + mi * (16 * BKP * 2) + s * 32);
                    #pragma unroll
                    for (int ni = 0; ni < 4; ni++)
                        mma_f16(acc[mi][ni], al0, al1, al2, al3, bh[ni][0], bh[ni][1]);
                }
            }
        }

        if (it + 2 < nKiter)
            stage((it + 2) % NSTG, (it + 2) * BK);
    }

    const int region = col0 >> 8;     // for EPI_QKV: 0=q, 1=k, 2=v
    #pragma unroll
    for (int mi = 0; mi < 4; mi++) {
        int r = row0 + warp_m * 64 + mi * 16 + g;
        #pragma unroll
        for (int ni = 0; ni < 4; ni++) {
            int c = col0 + warp_n * 32 + ni * 8 + 2 * t;
            float bx = bias[c], by = bias[c + 1];
            float4 d = acc[mi][ni];
            float v0 = d.x + bx, v1 = d.y + by;
            float v2 = d.z + bx, v3 = d.w + by;
            if (epi == EPI_QKV) {
                int local = c & 255;
                if (region == 0) {
                    if (r < M) {
                        g_q[(size_t)r * CC + local]     = v0 * QK_SCALE;
                        g_q[(size_t)r * CC + local + 1] = v1 * QK_SCALE;
                    }
                    if (r + 8 < M) {
                        g_q[(size_t)(r + 8) * CC + local]     = v2 * QK_SCALE;
                        g_q[(size_t)(r + 8) * CC + local + 1] = v3 * QK_SCALE;
                    }
                } else {
                    int h  = local >> 5;
                    int dd = (local & 31) + (region == 2 ? 32 : 0);
                    if (r < M) {
                        __half2 p; p.x = __float2half_rn(v0); p.y = __float2half_rn(v1);
                        *(__half2*)&g_kv[((size_t)r * HH + h) * 64 + dd] = p;
                    }
                    if (r + 8 < M) {
                        __half2 p; p.x = __float2half_rn(v2); p.y = __float2half_rn(v3);
                        *(__half2*)&g_kv[((size_t)(r + 8) * HH + h) * 64 + dd] = p;
                    }
                }
            } else if (epi == EPI_GELU) {
                v0 = fast_gelu(v0);
                v1 = fast_gelu(v1);
                v2 = fast_gelu(v2);
                v3 = fast_gelu(v3);
                if (r < M) {
                    size_t o = (size_t)r * Nn + c;
                    __half2 p; p.x = __float2half_rn(v0); p.y = __float2half_rn(v1);
                    *(__half2*)&Ch[o] = p;
                }
                if (r + 8 < M) {
                    size_t o = (size_t)(r + 8) * Nn + c;
                    __half2 p; p.x = __float2half_rn(v2); p.y = __float2half_rn(v3);
                    *(__half2*)&Ch[o] = p;
                }
            } else {
                if (r < M) {
                    size_t o = (size_t)r * Nn + c;
                    float r0 = resid[o], r1 = resid[o + 1];
                    Cf[o] = v0 + r0; Cf[o + 1] = v1 + r1;
                }
                if (r + 8 < M) {
                    size_t o = (size_t)(r + 8) * Nn + c;
                    float r2 = resid[o], r3 = resid[o + 1];
                    Cf[o] = v2 + r2; Cf[o + 1] = v3 + r3;
                }
            }
        }
    }
}

// ---------------- Edge-softmax attention -------------------------------------
// block per node; cp.async stages all neighbor KV lines (1KB each) into smem
// in 32-edge chunks; warp h computes head h from smem (lanes 0-15 k, 16-31 v).
#define ACH 32
__global__ __launch_bounds__(256)
void attn_kernel(__half* __restrict__ oh)
{
    __shared__ __align__(16) __half skv[ACH * 512];
    int n    = blockIdx.x;
    int tid  = threadIdx.x;
    int h    = tid >> 5;
    int lane = tid & 31;
    float2 q2 = make_float2(0.f, 0.f);
    if (lane < 16)
        q2 = *(const float2*)&g_q[(size_t)n * CC + h * HDIM + 2 * lane];
    int s = g_rowptr[n];
    int e = g_rowptr[n + 1];
    float m = -INFINITY, l = 0.0f;
    float2 acc = make_float2(0.f, 0.f);
    const uint32_t sbase = smem_u32(skv);

    for (int c0 = s; c0 < e; c0 += ACH) {
        int cnt = min(ACH, e - c0);
        __syncthreads();                       // smem reuse guard
        for (int idx = tid; idx < cnt * 64; idx += 256) {
            int ed  = idx >> 6;
            int c16 = idx & 63;
            const char* src = (const char*)(g_kv + (size_t)g_nbr[c0 + ed] * 512)
                              + c16 * 16;
            cp16(sbase + (uint32_t)(ed * 1024 + c16 * 16), src);
        }
        CP_COMMIT();
        CP_WAIT(0);
        __syncthreads();

        int u = 0;
        for (; u + 3 < cnt; u += 4) {
            float2 fv[4];
            float d[4];
            #pragma unroll
            for (int k2 = 0; k2 < 4; k2++) {
                __half2 hv = *(const __half2*)&skv[(u + k2) * 512 + h * 64 + 2 * lane];
                fv[k2] = __half22float2(hv);
            }
            #pragma unroll
            for (int k2 = 0; k2 < 4; k2++)
                d[k2] = (lane < 16) ? (q2.x * fv[k2].x + q2.y * fv[k2].y) : 0.0f;
            #pragma unroll
            for (int o = 16; o; o >>= 1) {
                #pragma unroll
                for (int k2 = 0; k2 < 4; k2++)
                    d[k2] += __shfl_xor_sync(0xffffffffu, d[k2], o);
            }
            float mb = fmaxf(fmaxf(d[0], d[1]), fmaxf(d[2], d[3]));
            float mn = fmaxf(m, mb);
            float sc = __expf(m - mn);
            float p0 = __expf(d[0] - mn);
            float p1 = __expf(d[1] - mn);
            float p2 = __expf(d[2] - mn);
            float p3 = __expf(d[3] - mn);
            l = l * sc + (p0 + p1 + p2 + p3);
            acc.x = acc.x * sc + p0 * fv[0].x + p1 * fv[1].x + p2 * fv[2].x + p3 * fv[3].x;
            acc.y = acc.y * sc + p0 * fv[0].y + p1 * fv[1].y + p2 * fv[2].y + p3 * fv[3].y;
            m = mn;
        }
        for (; u < cnt; u++) {
            __half2 hv = *(const __half2*)&skv[u * 512 + h * 64 + 2 * lane];
            float2 f = __half22float2(hv);
            float d = (lane < 16) ? (q2.x * f.x + q2.y * f.y) : 0.0f;
            #pragma unroll
            for (int o = 16; o; o >>= 1) d += __shfl_xor_sync(0xffffffffu, d, o);
            float mn = fmaxf(m, d);
            float sc = __expf(m - mn);
            float p  = __expf(d - mn);
            l = l * sc + p;
            acc.x = acc.x * sc + p * f.x;
            acc.y = acc.y * sc + p * f.y;
            m = mn;
        }
    }
    if (lane >= 16) {
        float inv = (l > 0.0f) ? (1.0f / l) : 0.0f;
        __half2 p;
        p.x = __float2half_rn(acc.x * inv);
        p.y = __float2half_rn(acc.y * inv);
        *(__half2*)&oh[(size_t)n * CC + h * HDIM + 2 * (lane - 16)] = p;
    }
}

// ---------------- host launcher ---------------------------------------------
extern "C" void kernel_launch(void* const* d_in, const int* in_sizes, int n_in,
                              void* d_out, int out_size)
{
    const float* feats  = (const float*)d_in[0];
    const int*   ei     = (const int*)d_in[2];
    const float* ln1_g  = (const float*)d_in[3];
    const float* ln1_b  = (const float*)d_in[4];
    const float* qkv_w  = (const float*)d_in[5];
    const float* qkv_b  = (const float*)d_in[6];
    const float* proj_w = (const float*)d_in[7];
    const float* proj_b = (const float*)d_in[8];
    const float* ln2_g  = (const float*)d_in[9];
    const float* ln2_b  = (const float*)d_in[10];
    const float* fc1_w  = (const float*)d_in[11];
    const float* fc1_b  = (const float*)d_in[12];
    const float* fc2_w  = (const float*)d_in[13];
    const float* fc2_b  = (const float*)d_in[14];
    float* out = (float*)d_out;

    float *p_f2;
    cudaGetSymbolAddress((void**)&p_f2,  g_f2);
    __half *p_xn_h, *p_xn_l, *p_at_h, *p_y_h, *p_h1_h;
    cudaGetSymbolAddress((void**)&p_xn_h, g_xn_h);
    cudaGetSymbolAddress((void**)&p_xn_l, g_xn_l);
    cudaGetSymbolAddress((void**)&p_at_h, g_at_h);
    cudaGetSymbolAddress((void**)&p_y_h,  g_y_h);
    cudaGetSymbolAddress((void**)&p_h1_h, g_h1_h);
    __half *p_wqkv, *p_wprj, *p_wfc1, *p_wfc2;
    cudaGetSymbolAddress((void**)&p_wqkv, g_wqkv);
    cudaGetSymbolAddress((void**)&p_wprj, g_wprj);
    cudaGetSymbolAddress((void**)&p_wfc1, g_wfc1);
    cudaGetSymbolAddress((void**)&p_wfc2, g_wfc2);

    const int SMEM_BYTES = NSTG * STAGEB;   // 92160
    static int init_done = 0;
    static cudaStream_t sB;
    static cudaEvent_t evFork, evW, evJoin;
    if (!init_done) {
        cudaFuncSetAttribute(gemm_sp_kernel,
                             cudaFuncAttributeMaxDynamicSharedMemorySize, SMEM_BYTES);
        cudaStreamCreateWithFlags(&sB, cudaStreamNonBlocking);
        cudaEventCreateWithFlags(&evFork, cudaEventDisableTiming);
        cudaEventCreateWithFlags(&evW,    cudaEventDisableTiming);
        cudaEventCreateWithFlags(&evJoin, cudaEventDisableTiming);
        init_done = 1;
    }

    const int nscan = (NN + SCAN_B - 1) / SCAN_B;
    const int MROWS = (NN + BM - 1) / BM;

    // fork side stream
    cudaEventRecord(evFork, 0);
    cudaStreamWaitEvent(sB, evFork, 0);

    // ---- stream B: qkv weight round first (overlaps LN1), then CSR + rounds
    round_kernel<<<(3*CC*CC + 255)/256, 256, 0, sB>>>(qkv_w, p_wqkv, 3*CC*CC);
    cudaEventRecord(evW, sB);
    zero_cnt_kernel<<<(NN + 255) / 256, 256, 0, sB>>>();
    count_kernel<<<(MM + 255) / 256, 256, 0, sB>>>(ei);
    scan1_kernel<<<nscan, SCAN_B, 0, sB>>>();
    scan2_kernel<<<1, 128, 0, sB>>>(nscan);
    scan3_kernel<<<nscan, SCAN_B, 0, sB>>>();
    scatter_kernel<<<(MM + 255) / 256, 256, 0, sB>>>(ei);
    round_kernel<<<(CC*CC   + 255)/256, 256, 0, sB>>>(proj_w, p_wprj, CC*CC);
    round_kernel<<<(HIDN*CC + 255)/256, 256, 0, sB>>>(fc1_w, p_wfc1, HIDN*CC);
    round_kernel<<<(CC*HIDN + 255)/256, 256, 0, sB>>>(fc2_w, p_wfc2, CC*HIDN);
    cudaEventRecord(evJoin, sB);

    // ---- main stream
    ln_split_kernel<<<(NN + 7) / 8, 256>>>(feats, ln1_g, ln1_b, p_xn_h, p_xn_l);
    cudaStreamWaitEvent(0, evW, 0);     // need qkv weights

    // qkv merged: q cols 2-term, k/v cols 1-term (auto per block)
    {
        dim3 grid(768 / BN, MROWS);
        gemm_sp_kernel<<<grid, 256, SMEM_BYTES>>>(p_xn_h, p_xn_l, p_wqkv,
                                                  qkv_b, nullptr, nullptr, nullptr,
                                                  NN, 768, CC, EPI_QKV, -1);
    }

    // join: attention needs CSR; later GEMMs need rounded weights
    cudaStreamWaitEvent(0, evJoin, 0);

    attn_kernel<<<NN, 256>>>(p_at_h);

    // proj: 1-term
    {
        dim3 grid(CC / BN, MROWS);
        gemm_sp_kernel<<<grid, 256, SMEM_BYTES>>>(p_at_h, nullptr, p_wprj,
                                                  proj_b, feats, p_f2, nullptr,
                                                  NN, CC, CC, EPI_RES, 0);
    }

    // LN2 -> fp16 (hi only)
    ln_split_kernel<<<(NN + 7) / 8, 256>>>(p_f2, ln2_g, ln2_b, p_y_h, nullptr);

    // fc1 + gelu: 1-term
    {
        dim3 grid(HIDN / BN, MROWS);
        gemm_sp_kernel<<<grid, 256, SMEM_BYTES>>>(p_y_h, nullptr, p_wfc1,
                                                  fc1_b, nullptr, nullptr, p_h1_h,
                                                  NN, HIDN, CC, EPI_GELU, 0);
    }

    // fc2 + residual: 1-term
    {
        dim3 grid(CC / BN, MROWS);
        gemm_sp_kernel<<<grid, 256, SMEM_BYTES>>>(p_h1_h, nullptr, p_wfc2,
                                                  fc2_b, p_f2, out, nullptr,
                                                  NN, CC, HIDN, EPI_RES, 0);
    }
}

// round 15
// speedup vs baseline: 1.4434x; 1.4434x over previous
#include <cuda_runtime.h>
#include <cuda_fp16.h>
#include <cstdint>
#include <math.h>

#define NN   50000
#define CC   256
#define HH   8
#define HDIM 32
#define MM   800000
#define HIDN 1024
#define QK_SCALE 0.17677669529663687f
#define LN_EPS 1e-5f

// ---------------- scratch (static device globals; no allocation) -------------
__device__ __align__(16) float g_q  [NN * CC];            // scaled q (fp32)
__device__ __align__(16) __half g_kv[NN * HH * 64];       // [n][h][k32|v32] fp16
__device__ __align__(16) float g_f2 [NN * CC];
__device__ __align__(16) __half g_xn_h[NN * CC],  g_xn_l[NN * CC];
__device__ __align__(16) __half g_at_h[NN * CC];
__device__ __align__(16) __half g_y_h [NN * CC];
__device__ __align__(16) __half g_h1_h[NN * HIDN];
__device__ __align__(16) __half g_wqkv[3*CC*CC];
__device__ __align__(16) __half g_wprj[CC*CC];
__device__ __align__(16) __half g_wfc1[HIDN*CC];
__device__ __align__(16) __half g_wfc2[CC*HIDN];
__device__ int g_cnt[NN];
__device__ int g_rowptr[NN + 1];
__device__ int g_cursor[NN];
__device__ int g_bsums[128];
__device__ int g_nbr[MM];

// ---------------- common PTX helpers ------------------------------------------
__device__ __forceinline__ uint32_t smem_u32(const void* p) {
    uint32_t a;
    asm("{ .reg .u64 t; cvta.to.shared.u64 t, %1; cvt.u32.u64 %0, t; }" : "=r"(a) : "l"(p));
    return a;
}

__device__ __forceinline__ void cp16(uint32_t dst, const void* src) {
    asm volatile("cp.async.cg.shared.global [%0],[%1],16;\n" :: "r"(dst), "l"(src));
}
#define CP_COMMIT() asm volatile("cp.async.commit_group;\n")
#define CP_WAIT(n)  asm volatile("cp.async.wait_group %0;\n" :: "n"(n))

// ---------------- fp32 -> fp16 weight round ----------------------------------
__global__ void round_kernel(const float* __restrict__ w,
                             __half* __restrict__ wh, int n)
{
    int i = blockIdx.x * blockDim.x + threadIdx.x;
    if (i < n) wh[i] = __float2half_rn(w[i]);
}

// ---------------- CSR build --------------------------------------------------
__global__ void zero_cnt_kernel() {
    int i = blockIdx.x * blockDim.x + threadIdx.x;
    if (i < NN) g_cnt[i] = 0;
}

__global__ void count_kernel(const int* __restrict__ ei) {
    int e = blockIdx.x * blockDim.x + threadIdx.x;
    if (e < MM) atomicAdd(&g_cnt[ei[e]], 1);
}

#define SCAN_B 512
__global__ void scan1_kernel() {
    __shared__ int sh[SCAN_B];
    int tid = threadIdx.x;
    int i = blockIdx.x * SCAN_B + tid;
    int v = (i < NN) ? g_cnt[i] : 0;
    sh[tid] = v;
    __syncthreads();
    for (int off = 1; off < SCAN_B; off <<= 1) {
        int t = (tid >= off) ? sh[tid - off] : 0;
        __syncthreads();
        sh[tid] += t;
        __syncthreads();
    }
    if (i < NN) g_rowptr[i] = sh[tid] - v;
    if (tid == SCAN_B - 1) g_bsums[blockIdx.x] = sh[tid];
}

__global__ void scan2_kernel(int nb) {
    __shared__ int sh[128];
    int tid = threadIdx.x;
    int v = (tid < nb) ? g_bsums[tid] : 0;
    sh[tid] = v;
    __syncthreads();
    for (int off = 1; off < 128; off <<= 1) {
        int t = (tid >= off) ? sh[tid - off] : 0;
        __syncthreads();
        sh[tid] += t;
        __syncthreads();
    }
    if (tid < nb) g_bsums[tid] = sh[tid] - v;   // exclusive
}

__global__ void scan3_kernel() {
    int i = blockIdx.x * SCAN_B + threadIdx.x;
    if (i < NN) {
        int v = g_rowptr[i] + g_bsums[blockIdx.x];
        g_rowptr[i] = v;
        g_cursor[i] = v;
    }
    if (i == 0) g_rowptr[NN] = MM;
}

__global__ void scatter_kernel(const int* __restrict__ ei) {
    int e = blockIdx.x * blockDim.x + threadIdx.x;
    if (e < MM) {
        int n = ei[e];
        int p = atomicAdd(&g_cursor[n], 1);
        g_nbr[p] = ei[MM + e];
    }
}

// ---------------- LayerNorm -> fp16 (optionally split) ------------------------
__global__ void ln_split_kernel(const float* __restrict__ x, const float* __restrict__ g,
                                const float* __restrict__ b,
                                __half* __restrict__ yh, __half* __restrict__ yl)
{
    int row  = blockIdx.x * 8 + (threadIdx.x >> 5);
    int lane = threadIdx.x & 31;
    if (row >= NN) return;
    const float4* xr = (const float4*)(x + (size_t)row * CC);
    float4 a = xr[lane];
    float4 c = xr[lane + 32];
    float s = a.x + a.y + a.z + a.w + c.x + c.y + c.z + c.w;
    float q = a.x*a.x + a.y*a.y + a.z*a.z + a.w*a.w
            + c.x*c.x + c.y*c.y + c.z*c.z + c.w*c.w;
    #pragma unroll
    for (int o = 16; o; o >>= 1) {
        s += __shfl_xor_sync(0xffffffffu, s, o);
        q += __shfl_xor_sync(0xffffffffu, q, o);
    }
    float mean = s * (1.0f / CC);
    float var  = q * (1.0f / CC) - mean * mean;
    float rstd = rsqrtf(var + LN_EPS);
    const float4* gv = (const float4*)g;
    const float4* bv = (const float4*)b;
    float4 g1 = gv[lane], g2 = gv[lane + 32];
    float4 b1 = bv[lane], b2 = bv[lane + 32];
    float o1[4], o2[4];
    o1[0] = (a.x - mean) * rstd * g1.x + b1.x;
    o1[1] = (a.y - mean) * rstd * g1.y + b1.y;
    o1[2] = (a.z - mean) * rstd * g1.z + b1.z;
    o1[3] = (a.w - mean) * rstd * g1.w + b1.w;
    o2[0] = (c.x - mean) * rstd * g2.x + b2.x;
    o2[1] = (c.y - mean) * rstd * g2.y + b2.y;
    o2[2] = (c.z - mean) * rstd * g2.z + b2.z;
    o2[3] = (c.w - mean) * rstd * g2.w + b2.w;

    __half h1[4], h2[4];
    #pragma unroll
    for (int i = 0; i < 4; i++) {
        h1[i] = __float2half_rn(o1[i]);
        h2[i] = __float2half_rn(o2[i]);
    }
    size_t base = (size_t)row * CC;
    *(uint2*)&yh[base + lane * 4]       = *(uint2*)h1;
    *(uint2*)&yh[base + 128 + lane * 4] = *(uint2*)h2;
    if (yl) {
        __half l1[4], l2[4];
        #pragma unroll
        for (int i = 0; i < 4; i++) {
            l1[i] = __float2half_rn(o1[i] - __half2float(h1[i]));
            l2[i] = __float2half_rn(o2[i] - __half2float(h2[i]));
        }
        *(uint2*)&yl[base + lane * 4]       = *(uint2*)l1;
        *(uint2*)&yl[base + 128 + lane * 4] = *(uint2*)l2;
    }
}

// ---------------- fp16 compensated GEMM, 2-stage cp.async pipeline ------------
#define BM 128
#define BN 128
#define BK 32
#define BKP 40
#define TILE (BM * BKP)
#define ARRB (TILE * 2)
#define STAGEB (3 * ARRB)          // 30720 B per stage (Ah, Al, Bh)

#define EPI_QKV  0
#define EPI_GELU 1
#define EPI_RES  2

__device__ __forceinline__ void ldsm4(unsigned& r0, unsigned& r1, unsigned& r2,
                                      unsigned& r3, uint32_t addr)
{
    asm volatile("ldmatrix.sync.aligned.m8n8.x4.shared.b16 {%0,%1,%2,%3}, [%4];"
                 : "=r"(r0), "=r"(r1), "=r"(r2), "=r"(r3) : "r"(addr));
}

__device__ __forceinline__ void mma_f16(float4& d,
    unsigned a0, unsigned a1, unsigned a2, unsigned a3,
    unsigned b0, unsigned b1)
{
    asm volatile(
        "mma.sync.aligned.m16n8k16.row.col.f32.f16.f16.f32 "
        "{%0,%1,%2,%3},{%4,%5,%6,%7},{%8,%9},{%0,%1,%2,%3};"
        : "+f"(d.x), "+f"(d.y), "+f"(d.z), "+f"(d.w)
        : "r"(a0), "r"(a1), "r"(a2), "r"(a3), "r"(b0), "r"(b1));
}

// fast exact-enough gelu: x*sigmoid(1.59576912*x*(1+0.044715*x^2))
__device__ __forceinline__ float fast_gelu(float x) {
    float w = 1.59576912f * x * (1.0f + 0.044715f * x * x);
    return __fdividef(x, 1.0f + __expf(-w));
}

// two_term: 1 = always, 0 = never, -1 = auto (q columns only, for EPI_QKV)
__global__ __launch_bounds__(256, 2)
void gemm_sp_kernel(const __half* __restrict__ Ah, const __half* __restrict__ Al,
                    const __half* __restrict__ Bh,
                    const float* __restrict__ bias, const float* __restrict__ resid,
                    float* __restrict__ Cf, __half* __restrict__ Ch,
                    int M, int Nn, int Kk, int epi, int two_term)
{
    extern __shared__ __half smem[];
    const uint32_t sb0 = smem_u32(smem);

    const int tid  = threadIdx.x;
    const int row0 = blockIdx.y * BM;
    const int col0 = blockIdx.x * BN;
    const int tt   = (two_term >= 0) ? two_term : ((col0 >> 8) == 0 ? 1 : 0);
    const int warp   = tid >> 5;
    const int lane   = tid & 31;
    const int warp_m = warp >> 2;
    const int warp_n = warp & 3;
    const int g = lane >> 2;
    const int t = lane & 3;

    const int rowA = warp_m * 64 + (lane & 15);
    const int colA = 8 * (lane >> 4);
    const uint32_t offA = (uint32_t)(rowA * BKP + colA) * 2;
    const int rowB = warp_n * 32 + (lane & 7) + 8 * ((lane >> 4) & 1);
    const int colB = 8 * ((lane >> 3) & 1);
    const uint32_t offB = (uint32_t)(rowB * BKP + colB) * 2;

    const int ch0 = tid * 2;
    const int nKiter = Kk / BK;

    float4 acc[4][4];
    #pragma unroll
    for (int i = 0; i < 4; i++)
        #pragma unroll
        for (int j = 0; j < 4; j++) acc[i][j] = make_float4(0.f, 0.f, 0.f, 0.f);

    auto stage = [&](int st, int k0) {
        uint32_t base = sb0 + st * STAGEB;
        #pragma unroll
        for (int q = 0; q < 2; q++) {
            int idx = ch0 + q;
            int r    = idx >> 2;
            int c16  = idx & 3;
            int ar = row0 + r; if (ar >= M) ar = M - 1;
            size_t aoff = (size_t)ar * Kk + k0 + c16 * 8;
            int br = col0 + r;
            size_t boff = (size_t)br * Kk + k0 + c16 * 8;
            uint32_t d = (uint32_t)(r * BKP + c16 * 8) * 2;
            cp16(base + 0 * ARRB + d, Ah + aoff);
            if (tt) cp16(base + 1 * ARRB + d, Al + aoff);
            cp16(base + 2 * ARRB + d, Bh + boff);
        }
    };

    stage(0, 0);
    CP_COMMIT();

    for (int it = 0; it < nKiter; it++) {
        if (it + 1 < nKiter) {
            stage((it + 1) & 1, (it + 1) * BK);
            CP_COMMIT();
            CP_WAIT(1);
        } else {
            CP_WAIT(0);
        }
        __syncthreads();

        const uint32_t base = sb0 + (it & 1) * STAGEB;
        const uint32_t aAh = base + offA;
        const uint32_t aAl = base + ARRB + offA;
        const uint32_t aBh = base + 2 * ARRB + offB;

        #pragma unroll
        for (int s = 0; s < 2; s++) {
            unsigned bh[4][2];
            ldsm4(bh[0][0], bh[0][1], bh[1][0], bh[1][1], aBh + s * 32);
            ldsm4(bh[2][0], bh[2][1], bh[3][0], bh[3][1], aBh + 16 * BKP * 2 + s * 32);
            #pragma unroll
            for (int mi = 0; mi < 4; mi++) {
                unsigned ah0, ah1, ah2, ah3;
                ldsm4(ah0, ah1, ah2, ah3, aAh + mi * (16 * BKP * 2) + s * 32);
                #pragma unroll
                for (int ni = 0; ni < 4; ni++)
                    mma_f16(acc[mi][ni], ah0, ah1, ah2, ah3, bh[ni][0], bh[ni][1]);
                if (tt) {
                    unsigned al0, al1, al2, al3;
                    ldsm4(al0, al1, al2, al3, aAl + mi * (16 * BKP * 2) + s * 32);
                    #pragma unroll
                    for (int ni = 0; ni < 4; ni++)
                        mma_f16(acc[mi][ni], al0, al1, al2, al3, bh[ni][0], bh[ni][1]);
                }
            }
        }
        __syncthreads();
    }

    const int region = col0 >> 8;     // for EPI_QKV: 0=q, 1=k, 2=v
    #pragma unroll
    for (int mi = 0; mi < 4; mi++) {
        int r = row0 + warp_m * 64 + mi * 16 + g;
        #pragma unroll
        for (int ni = 0; ni < 4; ni++) {
            int c = col0 + warp_n * 32 + ni * 8 + 2 * t;
            float bx = bias[c], by = bias[c + 1];
            float4 d = acc[mi][ni];
            float v0 = d.x + bx, v1 = d.y + by;
            float v2 = d.z + bx, v3 = d.w + by;
            if (epi == EPI_QKV) {
                int local = c & 255;
                if (region == 0) {
                    if (r < M) {
                        g_q[(size_t)r * CC + local]     = v0 * QK_SCALE;
                        g_q[(size_t)r * CC + local + 1] = v1 * QK_SCALE;
                    }
                    if (r + 8 < M) {
                        g_q[(size_t)(r + 8) * CC + local]     = v2 * QK_SCALE;
                        g_q[(size_t)(r + 8) * CC + local + 1] = v3 * QK_SCALE;
                    }
                } else {
                    int h  = local >> 5;
                    int dd = (local & 31) + (region == 2 ? 32 : 0);
                    if (r < M) {
                        __half2 p; p.x = __float2half_rn(v0); p.y = __float2half_rn(v1);
                        *(__half2*)&g_kv[((size_t)r * HH + h) * 64 + dd] = p;
                    }
                    if (r + 8 < M) {
                        __half2 p; p.x = __float2half_rn(v2); p.y = __float2half_rn(v3);
                        *(__half2*)&g_kv[((size_t)(r + 8) * HH + h) * 64 + dd] = p;
                    }
                }
            } else if (epi == EPI_GELU) {
                v0 = fast_gelu(v0);
                v1 = fast_gelu(v1);
                v2 = fast_gelu(v2);
                v3 = fast_gelu(v3);
                if (r < M) {
                    size_t o = (size_t)r * Nn + c;
                    __half2 p; p.x = __float2half_rn(v0); p.y = __float2half_rn(v1);
                    *(__half2*)&Ch[o] = p;
                }
                if (r + 8 < M) {
                    size_t o = (size_t)(r + 8) * Nn + c;
                    __half2 p; p.x = __float2half_rn(v2); p.y = __float2half_rn(v3);
                    *(__half2*)&Ch[o] = p;
                }
            } else {
                if (r < M) {
                    size_t o = (size_t)r * Nn + c;
                    float r0 = resid[o], r1 = resid[o + 1];
                    Cf[o] = v0 + r0; Cf[o + 1] = v1 + r1;
                }
                if (r + 8 < M) {
                    size_t o = (size_t)(r + 8) * Nn + c;
                    float r2 = resid[o], r3 = resid[o + 1];
                    Cf[o] = v2 + r2; Cf[o + 1] = v3 + r3;
                }
            }
        }
    }
}

// ---------------- Edge-softmax attention -------------------------------------
// block per node; cp.async stages all neighbor KV lines (1KB each) into smem
// in 32-edge chunks; warp h computes head h from smem (lanes 0-15 k, 16-31 v).
#define ACH 32
__global__ __launch_bounds__(256)
void attn_kernel(__half* __restrict__ oh)
{
    __shared__ __align__(16) __half skv[ACH * 512];
    int n    = blockIdx.x;
    int tid  = threadIdx.x;
    int h    = tid >> 5;
    int lane = tid & 31;
    float2 q2 = make_float2(0.f, 0.f);
    if (lane < 16)
        q2 = *(const float2*)&g_q[(size_t)n * CC + h * HDIM + 2 * lane];
    int s = g_rowptr[n];
    int e = g_rowptr[n + 1];
    float m = -INFINITY, l = 0.0f;
    float2 acc = make_float2(0.f, 0.f);
    const uint32_t sbase = smem_u32(skv);

    for (int c0 = s; c0 < e; c0 += ACH) {
        int cnt = min(ACH, e - c0);
        __syncthreads();                       // smem reuse guard
        for (int idx = tid; idx < cnt * 64; idx += 256) {
            int ed  = idx >> 6;
            int c16 = idx & 63;
            const char* src = (const char*)(g_kv + (size_t)g_nbr[c0 + ed] * 512)
                              + c16 * 16;
            cp16(sbase + (uint32_t)(ed * 1024 + c16 * 16), src);
        }
        CP_COMMIT();
        CP_WAIT(0);
        __syncthreads();

        int u = 0;
        for (; u + 3 < cnt; u += 4) {
            float2 fv[4];
            float d[4];
            #pragma unroll
            for (int k2 = 0; k2 < 4; k2++) {
                __half2 hv = *(const __half2*)&skv[(u + k2) * 512 + h * 64 + 2 * lane];
                fv[k2] = __half22float2(hv);
            }
            #pragma unroll
            for (int k2 = 0; k2 < 4; k2++)
                d[k2] = (lane < 16) ? (q2.x * fv[k2].x + q2.y * fv[k2].y) : 0.0f;
            #pragma unroll
            for (int o = 16; o; o >>= 1) {
                #pragma unroll
                for (int k2 = 0; k2 < 4; k2++)
                    d[k2] += __shfl_xor_sync(0xffffffffu, d[k2], o);
            }
            float mb = fmaxf(fmaxf(d[0], d[1]), fmaxf(d[2], d[3]));
            float mn = fmaxf(m, mb);
            float sc = __expf(m - mn);
            float p0 = __expf(d[0] - mn);
            float p1 = __expf(d[1] - mn);
            float p2 = __expf(d[2] - mn);
            float p3 = __expf(d[3] - mn);
            l = l * sc + (p0 + p1 + p2 + p3);
            acc.x = acc.x * sc + p0 * fv[0].x + p1 * fv[1].x + p2 * fv[2].x + p3 * fv[3].x;
            acc.y = acc.y * sc + p0 * fv[0].y + p1 * fv[1].y + p2 * fv[2].y + p3 * fv[3].y;
            m = mn;
        }
        for (; u < cnt; u++) {
            __half2 hv = *(const __half2*)&skv[u * 512 + h * 64 + 2 * lane];
            float2 f = __half22float2(hv);
            float d = (lane < 16) ? (q2.x * f.x + q2.y * f.y) : 0.0f;
            #pragma unroll
            for (int o = 16; o; o >>= 1) d += __shfl_xor_sync(0xffffffffu, d, o);
            float mn = fmaxf(m, d);
            float sc = __expf(m - mn);
            float p  = __expf(d - mn);
            l = l * sc + p;
            acc.x = acc.x * sc + p * f.x;
            acc.y = acc.y * sc + p * f.y;
            m = mn;
        }
    }
    if (lane >= 16) {
        float inv = (l > 0.0f) ? (1.0f / l) : 0.0f;
        __half2 p;
        p.x = __float2half_rn(acc.x * inv);
        p.y = __float2half_rn(acc.y * inv);
        *(__half2*)&oh[(size_t)n * CC + h * HDIM + 2 * (lane - 16)] = p;
    }
}

// ---------------- host launcher ---------------------------------------------
extern "C" void kernel_launch(void* const* d_in, const int* in_sizes, int n_in,
                              void* d_out, int out_size)
{
    const float* feats  = (const float*)d_in[0];
    const int*   ei     = (const int*)d_in[2];
    const float* ln1_g  = (const float*)d_in[3];
    const float* ln1_b  = (const float*)d_in[4];
    const float* qkv_w  = (const float*)d_in[5];
    const float* qkv_b  = (const float*)d_in[6];
    const float* proj_w = (const float*)d_in[7];
    const float* proj_b = (const float*)d_in[8];
    const float* ln2_g  = (const float*)d_in[9];
    const float* ln2_b  = (const float*)d_in[10];
    const float* fc1_w  = (const float*)d_in[11];
    const float* fc1_b  = (const float*)d_in[12];
    const float* fc2_w  = (const float*)d_in[13];
    const float* fc2_b  = (const float*)d_in[14];
    float* out = (float*)d_out;

    float *p_f2;
    cudaGetSymbolAddress((void**)&p_f2,  g_f2);
    __half *p_xn_h, *p_xn_l, *p_at_h, *p_y_h, *p_h1_h;
    cudaGetSymbolAddress((void**)&p_xn_h, g_xn_h);
    cudaGetSymbolAddress((void**)&p_xn_l, g_xn_l);
    cudaGetSymbolAddress((void**)&p_at_h, g_at_h);
    cudaGetSymbolAddress((void**)&p_y_h,  g_y_h);
    cudaGetSymbolAddress((void**)&p_h1_h, g_h1_h);
    __half *p_wqkv, *p_wprj, *p_wfc1, *p_wfc2;
    cudaGetSymbolAddress((void**)&p_wqkv, g_wqkv);
    cudaGetSymbolAddress((void**)&p_wprj, g_wprj);
    cudaGetSymbolAddress((void**)&p_wfc1, g_wfc1);
    cudaGetSymbolAddress((void**)&p_wfc2, g_wfc2);

    const int SMEM_BYTES = 2 * STAGEB;   // 61440 -> 2 CTAs/SM (proven config)
    static int init_done = 0;
    static cudaStream_t sB;
    static cudaEvent_t evFork, evW, evJoin;
    if (!init_done) {
        cudaFuncSetAttribute(gemm_sp_kernel,
                             cudaFuncAttributeMaxDynamicSharedMemorySize, SMEM_BYTES);
        cudaStreamCreateWithFlags(&sB, cudaStreamNonBlocking);
        cudaEventCreateWithFlags(&evFork, cudaEventDisableTiming);
        cudaEventCreateWithFlags(&evW,    cudaEventDisableTiming);
        cudaEventCreateWithFlags(&evJoin, cudaEventDisableTiming);
        init_done = 1;
    }

    const int nscan = (NN + SCAN_B - 1) / SCAN_B;
    const int MROWS = (NN + BM - 1) / BM;

    // fork side stream
    cudaEventRecord(evFork, 0);
    cudaStreamWaitEvent(sB, evFork, 0);

    // ---- stream B: qkv weight round first (overlaps LN1), then CSR + rounds
    round_kernel<<<(3*CC*CC + 255)/256, 256, 0, sB>>>(qkv_w, p_wqkv, 3*CC*CC);
    cudaEventRecord(evW, sB);
    zero_cnt_kernel<<<(NN + 255) / 256, 256, 0, sB>>>();
    count_kernel<<<(MM + 255) / 256, 256, 0, sB>>>(ei);
    scan1_kernel<<<nscan, SCAN_B, 0, sB>>>();
    scan2_kernel<<<1, 128, 0, sB>>>(nscan);
    scan3_kernel<<<nscan, SCAN_B, 0, sB>>>();
    scatter_kernel<<<(MM + 255) / 256, 256, 0, sB>>>(ei);
    round_kernel<<<(CC*CC   + 255)/256, 256, 0, sB>>>(proj_w, p_wprj, CC*CC);
    round_kernel<<<(HIDN*CC + 255)/256, 256, 0, sB>>>(fc1_w, p_wfc1, HIDN*CC);
    round_kernel<<<(CC*HIDN + 255)/256, 256, 0, sB>>>(fc2_w, p_wfc2, CC*HIDN);
    cudaEventRecord(evJoin, sB);

    // ---- main stream
    ln_split_kernel<<<(NN + 7) / 8, 256>>>(feats, ln1_g, ln1_b, p_xn_h, p_xn_l);
    cudaStreamWaitEvent(0, evW, 0);     // need qkv weights

    // qkv merged: q cols 2-term, k/v cols 1-term (auto per block)
    {
        dim3 grid(768 / BN, MROWS);
        gemm_sp_kernel<<<grid, 256, SMEM_BYTES>>>(p_xn_h, p_xn_l, p_wqkv,
                                                  qkv_b, nullptr, nullptr, nullptr,
                                                  NN, 768, CC, EPI_QKV, -1);
    }

    // join: attention needs CSR; later GEMMs need rounded weights
    cudaStreamWaitEvent(0, evJoin, 0);

    attn_kernel<<<NN, 256>>>(p_at_h);

    // proj: 1-term
    {
        dim3 grid(CC / BN, MROWS);
        gemm_sp_kernel<<<grid, 256, SMEM_BYTES>>>(p_at_h, nullptr, p_wprj,
                                                  proj_b, feats, p_f2, nullptr,
                                                  NN, CC, CC, EPI_RES, 0);
    }

    // LN2 -> fp16 (hi only)
    ln_split_kernel<<<(NN + 7) / 8, 256>>>(p_f2, ln2_g, ln2_b, p_y_h, nullptr);

    // fc1 + gelu: 1-term
    {
        dim3 grid(HIDN / BN, MROWS);
        gemm_sp_kernel<<<grid, 256, SMEM_BYTES>>>(p_y_h, nullptr, p_wfc1,
                                                  fc1_b, nullptr, nullptr, p_h1_h,
                                                  NN, HIDN, CC, EPI_GELU, 0);
    }

    // fc2 + residual: 1-term
    {
        dim3 grid(CC / BN, MROWS);
        gemm_sp_kernel<<<grid, 256, SMEM_BYTES>>>(p_h1_h, nullptr, p_wfc2,
                                                  fc2_b, p_f2, out, nullptr,
                                                  NN, CC, HIDN, EPI_RES, 0);
    }
}

// round 16
// speedup vs baseline: 1.5166x; 1.0507x over previous
#include <cuda_runtime.h>
#include <cuda_fp16.h>
#include <cstdint>
#include <math.h>

#define NN   50000
#define CC   256
#define HH   8
#define HDIM 32
#define MM   800000
#define HIDN 1024
#define QK_SCALE 0.17677669529663687f
#define LN_EPS 1e-5f

// ---------------- scratch (static device globals; no allocation) -------------
__device__ __align__(16) float g_q  [NN * CC];            // scaled q (fp32)
__device__ __align__(16) __half g_kv[NN * HH * 64];       // [n][h][k32|v32] fp16
__device__ __align__(16) float g_f2 [NN * CC];
__device__ __align__(16) __half g_xn_h[NN * CC],  g_xn_l[NN * CC];
__device__ __align__(16) __half g_at_h[NN * CC];
__device__ __align__(16) __half g_y_h [NN * CC];
__device__ __align__(16) __half g_h1_h[NN * HIDN];
__device__ __align__(16) __half g_wqkv[3*CC*CC];
__device__ __align__(16) __half g_wprj[CC*CC];
__device__ __align__(16) __half g_wfc1[HIDN*CC];
__device__ __align__(16) __half g_wfc2[CC*HIDN];
__device__ int g_cnt[NN];
__device__ int g_rowptr[NN + 1];
__device__ int g_cursor[NN];
__device__ int g_bsums[128];
__device__ int g_nbr[MM];

// ---------------- common PTX helpers ------------------------------------------
__device__ __forceinline__ uint32_t smem_u32(const void* p) {
    uint32_t a;
    asm("{ .reg .u64 t; cvta.to.shared.u64 t, %1; cvt.u32.u64 %0, t; }" : "=r"(a) : "l"(p));
    return a;
}

__device__ __forceinline__ void cp16(uint32_t dst, const void* src) {
    asm volatile("cp.async.cg.shared.global [%0],[%1],16;\n" :: "r"(dst), "l"(src));
}
#define CP_COMMIT() asm volatile("cp.async.commit_group;\n")
#define CP_WAIT(n)  asm volatile("cp.async.wait_group %0;\n" :: "n"(n))

// ---------------- fp32 -> fp16 weight round ----------------------------------
__global__ void round_kernel(const float* __restrict__ w,
                             __half* __restrict__ wh, int n)
{
    int i = blockIdx.x * blockDim.x + threadIdx.x;
    if (i < n) wh[i] = __float2half_rn(w[i]);
}

// ---------------- CSR build --------------------------------------------------
__global__ void count_kernel(const int* __restrict__ ei) {
    int e = blockIdx.x * blockDim.x + threadIdx.x;
    if (e < MM) atomicAdd(&g_cnt[ei[e]], 1);
}

#define SCAN_B 512
__global__ void scan1_kernel() {
    __shared__ int sh[SCAN_B];
    int tid = threadIdx.x;
    int i = blockIdx.x * SCAN_B + tid;
    int v = (i < NN) ? g_cnt[i] : 0;
    sh[tid] = v;
    __syncthreads();
    for (int off = 1; off < SCAN_B; off <<= 1) {
        int t = (tid >= off) ? sh[tid - off] : 0;
        __syncthreads();
        sh[tid] += t;
        __syncthreads();
    }
    if (i < NN) g_rowptr[i] = sh[tid] - v;
    if (tid == SCAN_B - 1) g_bsums[blockIdx.x] = sh[tid];
}

__global__ void scan2_kernel(int nb) {
    __shared__ int sh[128];
    int tid = threadIdx.x;
    int v = (tid < nb) ? g_bsums[tid] : 0;
    sh[tid] = v;
    __syncthreads();
    for (int off = 1; off < 128; off <<= 1) {
        int t = (tid >= off) ? sh[tid - off] : 0;
        __syncthreads();
        sh[tid] += t;
        __syncthreads();
    }
    if (tid < nb) g_bsums[tid] = sh[tid] - v;   // exclusive
}

__global__ void scan3_kernel() {
    int i = blockIdx.x * SCAN_B + threadIdx.x;
    if (i < NN) {
        int v = g_rowptr[i] + g_bsums[blockIdx.x];
        g_rowptr[i] = v;
        g_cursor[i] = v;
    }
    if (i == 0) g_rowptr[NN] = MM;
}

__global__ void scatter_kernel(const int* __restrict__ ei) {
    int e = blockIdx.x * blockDim.x + threadIdx.x;
    if (e < MM) {
        int n = ei[e];
        int p = atomicAdd(&g_cursor[n], 1);
        g_nbr[p] = ei[MM + e];
    }
}

// ---------------- LayerNorm -> fp16 (optionally split) ------------------------
__global__ void ln_split_kernel(const float* __restrict__ x, const float* __restrict__ g,
                                const float* __restrict__ b,
                                __half* __restrict__ yh, __half* __restrict__ yl)
{
    int row  = blockIdx.x * 8 + (threadIdx.x >> 5);
    int lane = threadIdx.x & 31;
    if (row >= NN) return;
    const float4* xr = (const float4*)(x + (size_t)row * CC);
    float4 a = xr[lane];
    float4 c = xr[lane + 32];
    float s = a.x + a.y + a.z + a.w + c.x + c.y + c.z + c.w;
    float q = a.x*a.x + a.y*a.y + a.z*a.z + a.w*a.w
            + c.x*c.x + c.y*c.y + c.z*c.z + c.w*c.w;
    #pragma unroll
    for (int o = 16; o; o >>= 1) {
        s += __shfl_xor_sync(0xffffffffu, s, o);
        q += __shfl_xor_sync(0xffffffffu, q, o);
    }
    float mean = s * (1.0f / CC);
    float var  = q * (1.0f / CC) - mean * mean;
    float rstd = rsqrtf(var + LN_EPS);
    const float4* gv = (const float4*)g;
    const float4* bv = (const float4*)b;
    float4 g1 = gv[lane], g2 = gv[lane + 32];
    float4 b1 = bv[lane], b2 = bv[lane + 32];
    float o1[4], o2[4];
    o1[0] = (a.x - mean) * rstd * g1.x + b1.x;
    o1[1] = (a.y - mean) * rstd * g1.y + b1.y;
    o1[2] = (a.z - mean) * rstd * g1.z + b1.z;
    o1[3] = (a.w - mean) * rstd * g1.w + b1.w;
    o2[0] = (c.x - mean) * rstd * g2.x + b2.x;
    o2[1] = (c.y - mean) * rstd * g2.y + b2.y;
    o2[2] = (c.z - mean) * rstd * g2.z + b2.z;
    o2[3] = (c.w - mean) * rstd * g2.w + b2.w;

    __half h1[4], h2[4];
    #pragma unroll
    for (int i = 0; i < 4; i++) {
        h1[i] = __float2half_rn(o1[i]);
        h2[i] = __float2half_rn(o2[i]);
    }
    size_t base = (size_t)row * CC;
    *(uint2*)&yh[base + lane * 4]       = *(uint2*)h1;
    *(uint2*)&yh[base + 128 + lane * 4] = *(uint2*)h2;
    if (yl) {
        __half l1[4], l2[4];
        #pragma unroll
        for (int i = 0; i < 4; i++) {
            l1[i] = __float2half_rn(o1[i] - __half2float(h1[i]));
            l2[i] = __float2half_rn(o2[i] - __half2float(h2[i]));
        }
        *(uint2*)&yl[base + lane * 4]       = *(uint2*)l1;
        *(uint2*)&yl[base + 128 + lane * 4] = *(uint2*)l2;
    }
}

// ---------------- fp16 compensated GEMM, 2-stage, 1 barrier/iter --------------
#define BM 128
#define BN 128
#define BK 32
#define BKP 40
#define TILE (BM * BKP)
#define ARRB (TILE * 2)
#define STAGEB (3 * ARRB)          // 30720 B per stage (Ah, Al, Bh)

#define EPI_QKV  0
#define EPI_GELU 1
#define EPI_RES  2

__device__ __forceinline__ void ldsm4(unsigned& r0, unsigned& r1, unsigned& r2,
                                      unsigned& r3, uint32_t addr)
{
    asm volatile("ldmatrix.sync.aligned.m8n8.x4.shared.b16 {%0,%1,%2,%3}, [%4];"
                 : "=r"(r0), "=r"(r1), "=r"(r2), "=r"(r3) : "r"(addr));
}

__device__ __forceinline__ void mma_f16(float4& d,
    unsigned a0, unsigned a1, unsigned a2, unsigned a3,
    unsigned b0, unsigned b1)
{
    asm volatile(
        "mma.sync.aligned.m16n8k16.row.col.f32.f16.f16.f32 "
        "{%0,%1,%2,%3},{%4,%5,%6,%7},{%8,%9},{%0,%1,%2,%3};"
        : "+f"(d.x), "+f"(d.y), "+f"(d.z), "+f"(d.w)
        : "r"(a0), "r"(a1), "r"(a2), "r"(a3), "r"(b0), "r"(b1));
}

// fast exact-enough gelu
__device__ __forceinline__ float fast_gelu(float x) {
    float w = 1.59576912f * x * (1.0f + 0.044715f * x * x);
    return __fdividef(x, 1.0f + __expf(-w));
}

// two_term: 1 = always, 0 = never, -1 = auto (q columns only, for EPI_QKV)
__global__ __launch_bounds__(256, 2)
void gemm_sp_kernel(const __half* __restrict__ Ah, const __half* __restrict__ Al,
                    const __half* __restrict__ Bh,
                    const float* __restrict__ bias, const float* __restrict__ resid,
                    float* __restrict__ Cf, __half* __restrict__ Ch,
                    int M, int Nn, int Kk, int epi, int two_term)
{
    extern __shared__ __half smem[];
    const uint32_t sb0 = smem_u32(smem);

    const int tid  = threadIdx.x;
    const int row0 = blockIdx.y * BM;
    const int col0 = blockIdx.x * BN;
    const int tt   = (two_term >= 0) ? two_term : ((col0 >> 8) == 0 ? 1 : 0);
    const int warp   = tid >> 5;
    const int lane   = tid & 31;
    const int warp_m = warp >> 2;
    const int warp_n = warp & 3;
    const int g = lane >> 2;
    const int t = lane & 3;

    const int rowA = warp_m * 64 + (lane & 15);
    const int colA = 8 * (lane >> 4);
    const uint32_t offA = (uint32_t)(rowA * BKP + colA) * 2;
    const int rowB = warp_n * 32 + (lane & 7) + 8 * ((lane >> 4) & 1);
    const int colB = 8 * ((lane >> 3) & 1);
    const uint32_t offB = (uint32_t)(rowB * BKP + colB) * 2;

    const int ch0 = tid * 2;
    const int nKiter = Kk / BK;

    float4 acc[4][4];
    #pragma unroll
    for (int i = 0; i < 4; i++)
        #pragma unroll
        for (int j = 0; j < 4; j++) acc[i][j] = make_float4(0.f, 0.f, 0.f, 0.f);

    auto stage = [&](int st, int k0) {
        uint32_t base = sb0 + st * STAGEB;
        #pragma unroll
        for (int q = 0; q < 2; q++) {
            int idx = ch0 + q;
            int r    = idx >> 2;
            int c16  = idx & 3;
            int ar = row0 + r; if (ar >= M) ar = M - 1;
            size_t aoff = (size_t)ar * Kk + k0 + c16 * 8;
            int br = col0 + r;
            size_t boff = (size_t)br * Kk + k0 + c16 * 8;
            uint32_t d = (uint32_t)(r * BKP + c16 * 8) * 2;
            cp16(base + 0 * ARRB + d, Ah + aoff);
            if (tt) cp16(base + 1 * ARRB + d, Al + aoff);
            cp16(base + 2 * ARRB + d, Bh + boff);
        }
        CP_COMMIT();
    };

    stage(0, 0);

    for (int it = 0; it < nKiter; it++) {
        CP_WAIT(0);
        __syncthreads();     // publishes staged data; also guards buffer reuse
        if (it + 1 < nKiter)
            stage((it + 1) & 1, (it + 1) * BK);   // overlaps compute below

        const uint32_t base = sb0 + (it & 1) * STAGEB;
        const uint32_t aAh = base + offA;
        const uint32_t aAl = base + ARRB + offA;
        const uint32_t aBh = base + 2 * ARRB + offB;

        #pragma unroll
        for (int s = 0; s < 2; s++) {
            unsigned bh[4][2];
            ldsm4(bh[0][0], bh[0][1], bh[1][0], bh[1][1], aBh + s * 32);
            ldsm4(bh[2][0], bh[2][1], bh[3][0], bh[3][1], aBh + 16 * BKP * 2 + s * 32);
            #pragma unroll
            for (int mi = 0; mi < 4; mi++) {
                unsigned ah0, ah1, ah2, ah3;
                ldsm4(ah0, ah1, ah2, ah3, aAh + mi * (16 * BKP * 2) + s * 32);
                #pragma unroll
                for (int ni = 0; ni < 4; ni++)
                    mma_f16(acc[mi][ni], ah0, ah1, ah2, ah3, bh[ni][0], bh[ni][1]);
                if (tt) {
                    unsigned al0, al1, al2, al3;
                    ldsm4(al0, al1, al2, al3, aAl + mi * (16 * BKP * 2) + s * 32);
                    #pragma unroll
                    for (int ni = 0; ni < 4; ni++)
                        mma_f16(acc[mi][ni], al0, al1, al2, al3, bh[ni][0], bh[ni][1]);
                }
            }
        }
    }

    const int region = col0 >> 8;     // for EPI_QKV: 0=q, 1=k, 2=v
    #pragma unroll
    for (int mi = 0; mi < 4; mi++) {
        int r = row0 + warp_m * 64 + mi * 16 + g;
        #pragma unroll
        for (int ni = 0; ni < 4; ni++) {
            int c = col0 + warp_n * 32 + ni * 8 + 2 * t;
            float bx = bias[c], by = bias[c + 1];
            float4 d = acc[mi][ni];
            float v0 = d.x + bx, v1 = d.y + by;
            float v2 = d.z + bx, v3 = d.w + by;
            if (epi == EPI_QKV) {
                int local = c & 255;
                if (region == 0) {
                    if (r < M) {
                        g_q[(size_t)r * CC + local]     = v0 * QK_SCALE;
                        g_q[(size_t)r * CC + local + 1] = v1 * QK_SCALE;
                    }
                    if (r + 8 < M) {
                        g_q[(size_t)(r + 8) * CC + local]     = v2 * QK_SCALE;
                        g_q[(size_t)(r + 8) * CC + local + 1] = v3 * QK_SCALE;
                    }
                } else {
                    int h  = local >> 5;
                    int dd = (local & 31) + (region == 2 ? 32 : 0);
                    if (r < M) {
                        __half2 p; p.x = __float2half_rn(v0); p.y = __float2half_rn(v1);
                        *(__half2*)&g_kv[((size_t)r * HH + h) * 64 + dd] = p;
                    }
                    if (r + 8 < M) {
                        __half2 p; p.x = __float2half_rn(v2); p.y = __float2half_rn(v3);
                        *(__half2*)&g_kv[((size_t)(r + 8) * HH + h) * 64 + dd] = p;
                    }
                }
            } else if (epi == EPI_GELU) {
                v0 = fast_gelu(v0);
                v1 = fast_gelu(v1);
                v2 = fast_gelu(v2);
                v3 = fast_gelu(v3);
                if (r < M) {
                    size_t o = (size_t)r * Nn + c;
                    __half2 p; p.x = __float2half_rn(v0); p.y = __float2half_rn(v1);
                    *(__half2*)&Ch[o] = p;
                }
                if (r + 8 < M) {
                    size_t o = (size_t)(r + 8) * Nn + c;
                    __half2 p; p.x = __float2half_rn(v2); p.y = __float2half_rn(v3);
                    *(__half2*)&Ch[o] = p;
                }
            } else {
                if (r < M) {
                    size_t o = (size_t)r * Nn + c;
                    float r0 = resid[o], r1 = resid[o + 1];
                    Cf[o] = v0 + r0; Cf[o + 1] = v1 + r1;
                }
                if (r + 8 < M) {
                    size_t o = (size_t)(r + 8) * Nn + c;
                    float r2 = resid[o], r3 = resid[o + 1];
                    Cf[o] = v2 + r2; Cf[o + 1] = v3 + r3;
                }
            }
        }
    }
}

// ---------------- Edge-softmax attention -------------------------------------
// block per node; smem-staged KV; paired-edge reduce: lo half-warp computes
// edge e0's dot, hi half computes e1's -> 5 shfls per 2 edges. v-acc: lane=dim.
#define ACH 32
__global__ __launch_bounds__(256)
void attn_kernel(__half* __restrict__ oh)
{
    __shared__ __align__(16) __half skv[ACH * 512];
    int n    = blockIdx.x;
    int tid  = threadIdx.x;
    int h    = tid >> 5;
    int lane = tid & 31;
    // q replicated on both half-warps: dims (2*(lane&15), +1)
    float2 q2 = *(const float2*)&g_q[(size_t)n * CC + h * HDIM + 2 * (lane & 15)];
    int s = g_rowptr[n];
    int e = g_rowptr[n + 1];
    float m = -INFINITY, l = 0.0f;
    float accv = 0.0f;                         // v accumulation, dim = lane
    const uint32_t sbase = smem_u32(skv);
    const __half2* skv2 = (const __half2*)skv;
    const bool lo = (lane < 16);

    for (int c0 = s; c0 < e; c0 += ACH) {
        int cnt = min(ACH, e - c0);
        __syncthreads();                       // smem reuse guard
        for (int idx = tid; idx < cnt * 64; idx += 256) {
            int ed  = idx >> 6;
            int c16 = idx & 63;
            const char* src = (const char*)(g_kv + (size_t)g_nbr[c0 + ed] * 512)
                              + c16 * 16;
            cp16(sbase + (uint32_t)(ed * 1024 + c16 * 16), src);
        }
        CP_COMMIT();
        CP_WAIT(0);
        __syncthreads();

        int u = 0;
        for (; u + 3 < cnt; u += 4) {          // 2 pairs per batch
            float part[2];
            #pragma unroll
            for (int p = 0; p < 2; p++) {
                int ed = u + 2 * p + (lo ? 0 : 1);
                __half2 kh = skv2[ed * 256 + h * 32 + (lane & 15)];
                float2 kf = __half22float2(kh);
                part[p] = q2.x * kf.x + q2.y * kf.y;
            }
            #pragma unroll
            for (int o = 8; o; o >>= 1) {
                part[0] += __shfl_xor_sync(0xffffffffu, part[0], o);
                part[1] += __shfl_xor_sync(0xffffffffu, part[1], o);
            }
            float oth0 = __shfl_xor_sync(0xffffffffu, part[0], 16);
            float oth1 = __shfl_xor_sync(0xffffffffu, part[1], 16);
            float d0 = lo ? part[0] : oth0;    // edge u
            float d1 = lo ? oth0 : part[0];    // edge u+1
            float d2 = lo ? part[1] : oth1;    // edge u+2
            float d3 = lo ? oth1 : part[1];    // edge u+3
            float mb = fmaxf(fmaxf(d0, d1), fmaxf(d2, d3));
            float mn = fmaxf(m, mb);
            float sc = __expf(m - mn);
            float p0 = __expf(d0 - mn);
            float p1 = __expf(d1 - mn);
            float p2 = __expf(d2 - mn);
            float p3 = __expf(d3 - mn);
            l = l * sc + (p0 + p1 + p2 + p3);
            float v0 = __half2float(skv[(u    ) * 512 + h * 64 + 32 + lane]);
            float v1 = __half2float(skv[(u + 1) * 512 + h * 64 + 32 + lane]);
            float v2 = __half2float(skv[(u + 2) * 512 + h * 64 + 32 + lane]);
            float v3 = __half2float(skv[(u + 3) * 512 + h * 64 + 32 + lane]);
            accv = accv * sc + p0 * v0 + p1 * v1 + p2 * v2 + p3 * v3;
            m = mn;
        }
        for (; u < cnt; u++) {                 // tail: single edge
            __half2 kh = skv2[u * 256 + h * 32 + (lane & 15)];
            float2 kf = __half22float2(kh);
            float d = lo ? (q2.x * kf.x + q2.y * kf.y) : 0.0f;
            #pragma unroll
            for (int o = 16; o; o >>= 1) d += __shfl_xor_sync(0xffffffffu, d, o);
            float mn = fmaxf(m, d);
            float sc = __expf(m - mn);
            float p  = __expf(d - mn);
            l = l * sc + p;
            float vv = __half2float(skv[u * 512 + h * 64 + 32 + lane]);
            accv = accv * sc + p * vv;
            m = mn;
        }
    }
    float inv = (l > 0.0f) ? (1.0f / l) : 0.0f;
    oh[(size_t)n * CC + h * HDIM + lane] = __float2half_rn(accv * inv);
}

// ---------------- host launcher ---------------------------------------------
extern "C" void kernel_launch(void* const* d_in, const int* in_sizes, int n_in,
                              void* d_out, int out_size)
{
    const float* feats  = (const float*)d_in[0];
    const int*   ei     = (const int*)d_in[2];
    const float* ln1_g  = (const float*)d_in[3];
    const float* ln1_b  = (const float*)d_in[4];
    const float* qkv_w  = (const float*)d_in[5];
    const float* qkv_b  = (const float*)d_in[6];
    const float* proj_w = (const float*)d_in[7];
    const float* proj_b = (const float*)d_in[8];
    const float* ln2_g  = (const float*)d_in[9];
    const float* ln2_b  = (const float*)d_in[10];
    const float* fc1_w  = (const float*)d_in[11];
    const float* fc1_b  = (const float*)d_in[12];
    const float* fc2_w  = (const float*)d_in[13];
    const float* fc2_b  = (const float*)d_in[14];
    float* out = (float*)d_out;

    float *p_f2;
    cudaGetSymbolAddress((void**)&p_f2,  g_f2);
    __half *p_xn_h, *p_xn_l, *p_at_h, *p_y_h, *p_h1_h;
    cudaGetSymbolAddress((void**)&p_xn_h, g_xn_h);
    cudaGetSymbolAddress((void**)&p_xn_l, g_xn_l);
    cudaGetSymbolAddress((void**)&p_at_h, g_at_h);
    cudaGetSymbolAddress((void**)&p_y_h,  g_y_h);
    cudaGetSymbolAddress((void**)&p_h1_h, g_h1_h);
    __half *p_wqkv, *p_wprj, *p_wfc1, *p_wfc2;
    cudaGetSymbolAddress((void**)&p_wqkv, g_wqkv);
    cudaGetSymbolAddress((void**)&p_wprj, g_wprj);
    cudaGetSymbolAddress((void**)&p_wfc1, g_wfc1);
    cudaGetSymbolAddress((void**)&p_wfc2, g_wfc2);
    int* p_cnt;
    cudaGetSymbolAddress((void**)&p_cnt, g_cnt);

    const int SMEM_BYTES = 2 * STAGEB;   // 61440 -> 2 CTAs/SM (proven config)
    static int init_done = 0;
    static cudaStream_t sB;
    static cudaEvent_t evFork, evW, evJoin;
    if (!init_done) {
        cudaFuncSetAttribute(gemm_sp_kernel,
                             cudaFuncAttributeMaxDynamicSharedMemorySize, SMEM_BYTES);
        cudaStreamCreateWithFlags(&sB, cudaStreamNonBlocking);
        cudaEventCreateWithFlags(&evFork, cudaEventDisableTiming);
        cudaEventCreateWithFlags(&evW,    cudaEventDisableTiming);
        cudaEventCreateWithFlags(&evJoin, cudaEventDisableTiming);
        init_done = 1;
    }

    const int nscan = (NN + SCAN_B - 1) / SCAN_B;
    const int MROWS = (NN + BM - 1) / BM;

    // fork side stream
    cudaEventRecord(evFork, 0);
    cudaStreamWaitEvent(sB, evFork, 0);

    // ---- stream B: qkv weight round first (overlaps LN1), then CSR + rounds
    round_kernel<<<(3*CC*CC + 255)/256, 256, 0, sB>>>(qkv_w, p_wqkv, 3*CC*CC);
    cudaEventRecord(evW, sB);
    cudaMemsetAsync(p_cnt, 0, NN * sizeof(int), sB);
    count_kernel<<<(MM + 255) / 256, 256, 0, sB>>>(ei);
    scan1_kernel<<<nscan, SCAN_B, 0, sB>>>();
    scan2_kernel<<<1, 128, 0, sB>>>(nscan);
    scan3_kernel<<<nscan, SCAN_B, 0, sB>>>();
    scatter_kernel<<<(MM + 255) / 256, 256, 0, sB>>>(ei);
    round_kernel<<<(CC*CC   + 255)/256, 256, 0, sB>>>(proj_w, p_wprj, CC*CC);
    round_kernel<<<(HIDN*CC + 255)/256, 256, 0, sB>>>(fc1_w, p_wfc1, HIDN*CC);
    round_kernel<<<(CC*HIDN + 255)/256, 256, 0, sB>>>(fc2_w, p_wfc2, CC*HIDN);
    cudaEventRecord(evJoin, sB);

    // ---- main stream
    ln_split_kernel<<<(NN + 7) / 8, 256>>>(feats, ln1_g, ln1_b, p_xn_h, p_xn_l);
    cudaStreamWaitEvent(0, evW, 0);     // need qkv weights

    // qkv merged: q cols 2-term, k/v cols 1-term (auto per block)
    {
        dim3 grid(768 / BN, MROWS);
        gemm_sp_kernel<<<grid, 256, SMEM_BYTES>>>(p_xn_h, p_xn_l, p_wqkv,
                                                  qkv_b, nullptr, nullptr, nullptr,
                                                  NN, 768, CC, EPI_QKV, -1);
    }

    // join: attention needs CSR; later GEMMs need rounded weights
    cudaStreamWaitEvent(0, evJoin, 0);

    attn_kernel<<<NN, 256>>>(p_at_h);

    // proj: 1-term
    {
        dim3 grid(CC / BN, MROWS);
        gemm_sp_kernel<<<grid, 256, SMEM_BYTES>>>(p_at_h, nullptr, p_wprj,
                                                  proj_b, feats, p_f2, nullptr,
                                                  NN, CC, CC, EPI_RES, 0);
    }

    // LN2 -> fp16 (hi only)
    ln_split_kernel<<<(NN + 7) / 8, 256>>>(p_f2, ln2_g, ln2_b, p_y_h, nullptr);

    // fc1 + gelu: 1-term
    {
        dim3 grid(HIDN / BN, MROWS);
        gemm_sp_kernel<<<grid, 256, SMEM_BYTES>>>(p_y_h, nullptr, p_wfc1,
                                                  fc1_b, nullptr, nullptr, p_h1_h,
                                                  NN, HIDN, CC, EPI_GELU, 0);
    }

    // fc2 + residual: 1-term
    {
        dim3 grid(CC / BN, MROWS);
        gemm_sp_kernel<<<grid, 256, SMEM_BYTES>>>(p_h1_h, nullptr, p_wfc2,
                                                  fc2_b, p_f2, out, nullptr,
                                                  NN, CC, HIDN, EPI_RES, 0);
    }
}

// round 17
// speedup vs baseline: 1.7405x; 1.1476x over previous
#include <cuda_runtime.h>
#include <cuda_fp16.h>
#include <cstdint>
#include <math.h>

#define NN   50000
#define CC   256
#define HH   8
#define HDIM 32
#define MM   800000
#define HIDN 1024
#define QK_SCALE 0.17677669529663687f
#define LN_EPS 1e-5f

// ---------------- scratch (static device globals; no allocation) -------------
__device__ __align__(16) float g_q  [NN * CC];            // scaled q (fp32)
__device__ __align__(16) __half g_kv[NN * HH * 64];       // [n][h][k32|v32] fp16
__device__ __align__(16) float g_f2 [NN * CC];
__device__ __align__(16) __half g_xn_h[NN * CC];
__device__ __align__(16) __half g_at_h[NN * CC];
__device__ __align__(16) __half g_y_h [NN * CC];
__device__ __align__(16) __half g_h1_h[NN * HIDN];
__device__ __align__(16) __half g_wqkv[3*CC*CC];
__device__ __align__(16) __half g_wprj[CC*CC];
__device__ __align__(16) __half g_wfc1[HIDN*CC];
__device__ __align__(16) __half g_wfc2[CC*HIDN];
__device__ int g_cnt[NN];
__device__ int g_rowptr[NN + 1];
__device__ int g_cursor[NN];
__device__ int g_bsums[128];
__device__ int g_nbr[MM];

// ---------------- common PTX helpers ------------------------------------------
__device__ __forceinline__ uint32_t smem_u32(const void* p) {
    uint32_t a;
    asm("{ .reg .u64 t; cvta.to.shared.u64 t, %1; cvt.u32.u64 %0, t; }" : "=r"(a) : "l"(p));
    return a;
}

__device__ __forceinline__ void cp16(uint32_t dst, const void* src) {
    asm volatile("cp.async.cg.shared.global [%0],[%1],16;\n" :: "r"(dst), "l"(src));
}
#define CP_COMMIT() asm volatile("cp.async.commit_group;\n")
#define CP_WAIT(n)  asm volatile("cp.async.wait_group %0;\n" :: "n"(n))

// ---------------- fp32 -> fp16 weight round ----------------------------------
__global__ void round_kernel(const float* __restrict__ w,
                             __half* __restrict__ wh, int n)
{
    int i = blockIdx.x * blockDim.x + threadIdx.x;
    if (i < n) wh[i] = __float2half_rn(w[i]);
}

// ---------------- CSR build --------------------------------------------------
__global__ void count_kernel(const int* __restrict__ ei) {
    int e = blockIdx.x * blockDim.x + threadIdx.x;
    if (e < MM) atomicAdd(&g_cnt[ei[e]], 1);
}

#define SCAN_B 512
__global__ void scan1_kernel() {
    __shared__ int sh[SCAN_B];
    int tid = threadIdx.x;
    int i = blockIdx.x * SCAN_B + tid;
    int v = (i < NN) ? g_cnt[i] : 0;
    sh[tid] = v;
    __syncthreads();
    for (int off = 1; off < SCAN_B; off <<= 1) {
        int t = (tid >= off) ? sh[tid - off] : 0;
        __syncthreads();
        sh[tid] += t;
        __syncthreads();
    }
    if (i < NN) g_rowptr[i] = sh[tid] - v;
    if (tid == SCAN_B - 1) g_bsums[blockIdx.x] = sh[tid];
}

__global__ void scan2_kernel(int nb) {
    __shared__ int sh[128];
    int tid = threadIdx.x;
    int v = (tid < nb) ? g_bsums[tid] : 0;
    sh[tid] = v;
    __syncthreads();
    for (int off = 1; off < 128; off <<= 1) {
        int t = (tid >= off) ? sh[tid - off] : 0;
        __syncthreads();
        sh[tid] += t;
        __syncthreads();
    }
    if (tid < nb) g_bsums[tid] = sh[tid] - v;   // exclusive
}

__global__ void scan3_kernel() {
    int i = blockIdx.x * SCAN_B + threadIdx.x;
    if (i < NN) {
        int v = g_rowptr[i] + g_bsums[blockIdx.x];
        g_rowptr[i] = v;
        g_cursor[i] = v;
    }
    if (i == 0) g_rowptr[NN] = MM;
}

__global__ void scatter_kernel(const int* __restrict__ ei) {
    int e = blockIdx.x * blockDim.x + threadIdx.x;
    if (e < MM) {
        int n = ei[e];
        int p = atomicAdd(&g_cursor[n], 1);
        g_nbr[p] = ei[MM + e];
    }
}

// ---------------- LayerNorm -> fp16 -------------------------------------------
__global__ void ln_kernel(const float* __restrict__ x, const float* __restrict__ g,
                          const float* __restrict__ b, __half* __restrict__ yh)
{
    int row  = blockIdx.x * 8 + (threadIdx.x >> 5);
    int lane = threadIdx.x & 31;
    if (row >= NN) return;
    const float4* xr = (const float4*)(x + (size_t)row * CC);
    float4 a = xr[lane];
    float4 c = xr[lane + 32];
    float s = a.x + a.y + a.z + a.w + c.x + c.y + c.z + c.w;
    float q = a.x*a.x + a.y*a.y + a.z*a.z + a.w*a.w
            + c.x*c.x + c.y*c.y + c.z*c.z + c.w*c.w;
    #pragma unroll
    for (int o = 16; o; o >>= 1) {
        s += __shfl_xor_sync(0xffffffffu, s, o);
        q += __shfl_xor_sync(0xffffffffu, q, o);
    }
    float mean = s * (1.0f / CC);
    float var  = q * (1.0f / CC) - mean * mean;
    float rstd = rsqrtf(var + LN_EPS);
    const float4* gv = (const float4*)g;
    const float4* bv = (const float4*)b;
    float4 g1 = gv[lane], g2 = gv[lane + 32];
    float4 b1 = bv[lane], b2 = bv[lane + 32];
    __half h1[4], h2[4];
    h1[0] = __float2half_rn((a.x - mean) * rstd * g1.x + b1.x);
    h1[1] = __float2half_rn((a.y - mean) * rstd * g1.y + b1.y);
    h1[2] = __float2half_rn((a.z - mean) * rstd * g1.z + b1.z);
    h1[3] = __float2half_rn((a.w - mean) * rstd * g1.w + b1.w);
    h2[0] = __float2half_rn((c.x - mean) * rstd * g2.x + b2.x);
    h2[1] = __float2half_rn((c.y - mean) * rstd * g2.y + b2.y);
    h2[2] = __float2half_rn((c.z - mean) * rstd * g2.z + b2.z);
    h2[3] = __float2half_rn((c.w - mean) * rstd * g2.w + b2.w);
    size_t base = (size_t)row * CC;
    *(uint2*)&yh[base + lane * 4]       = *(uint2*)h1;
    *(uint2*)&yh[base + 128 + lane * 4] = *(uint2*)h2;
}

// ---------------- fp16 GEMM, 2-stage, 1 barrier/iter --------------------------
#define BM 128
#define BN 128
#define BK 32
#define BKP 40
#define TILE (BM * BKP)
#define ARRB (TILE * 2)
#define STAGEB (2 * ARRB)          // 20480 B per stage (Ah, Bh)

#define EPI_QKV  0
#define EPI_GELU 1
#define EPI_RES  2

__device__ __forceinline__ void ldsm4(unsigned& r0, unsigned& r1, unsigned& r2,
                                      unsigned& r3, uint32_t addr)
{
    asm volatile("ldmatrix.sync.aligned.m8n8.x4.shared.b16 {%0,%1,%2,%3}, [%4];"
                 : "=r"(r0), "=r"(r1), "=r"(r2), "=r"(r3) : "r"(addr));
}

__device__ __forceinline__ void mma_f16(float4& d,
    unsigned a0, unsigned a1, unsigned a2, unsigned a3,
    unsigned b0, unsigned b1)
{
    asm volatile(
        "mma.sync.aligned.m16n8k16.row.col.f32.f16.f16.f32 "
        "{%0,%1,%2,%3},{%4,%5,%6,%7},{%8,%9},{%0,%1,%2,%3};"
        : "+f"(d.x), "+f"(d.y), "+f"(d.z), "+f"(d.w)
        : "r"(a0), "r"(a1), "r"(a2), "r"(a3), "r"(b0), "r"(b1));
}

__device__ __forceinline__ float fast_gelu(float x) {
    float w = 1.59576912f * x * (1.0f + 0.044715f * x * x);
    return __fdividef(x, 1.0f + __expf(-w));
}

__global__ __launch_bounds__(256, 2)
void gemm_sp_kernel(const __half* __restrict__ Ah, const __half* __restrict__ Bh,
                    const float* __restrict__ bias, const float* __restrict__ resid,
                    float* __restrict__ Cf, __half* __restrict__ Ch,
                    int M, int Nn, int Kk, int epi)
{
    extern __shared__ __half smem[];
    const uint32_t sb0 = smem_u32(smem);

    const int tid  = threadIdx.x;
    const int row0 = blockIdx.y * BM;
    const int col0 = blockIdx.x * BN;
    const int warp   = tid >> 5;
    const int lane   = tid & 31;
    const int warp_m = warp >> 2;
    const int warp_n = warp & 3;
    const int g = lane >> 2;
    const int t = lane & 3;

    const int rowA = warp_m * 64 + (lane & 15);
    const int colA = 8 * (lane >> 4);
    const uint32_t offA = (uint32_t)(rowA * BKP + colA) * 2;
    const int rowB = warp_n * 32 + (lane & 7) + 8 * ((lane >> 4) & 1);
    const int colB = 8 * ((lane >> 3) & 1);
    const uint32_t offB = (uint32_t)(rowB * BKP + colB) * 2;

    const int ch0 = tid * 2;
    const int nKiter = Kk / BK;

    float4 acc[4][4];
    #pragma unroll
    for (int i = 0; i < 4; i++)
        #pragma unroll
        for (int j = 0; j < 4; j++) acc[i][j] = make_float4(0.f, 0.f, 0.f, 0.f);

    auto stage = [&](int st, int k0) {
        uint32_t base = sb0 + st * STAGEB;
        #pragma unroll
        for (int q = 0; q < 2; q++) {
            int idx = ch0 + q;
            int r    = idx >> 2;
            int c16  = idx & 3;
            int ar = row0 + r; if (ar >= M) ar = M - 1;
            size_t aoff = (size_t)ar * Kk + k0 + c16 * 8;
            int br = col0 + r;
            size_t boff = (size_t)br * Kk + k0 + c16 * 8;
            uint32_t d = (uint32_t)(r * BKP + c16 * 8) * 2;
            cp16(base + d, Ah + aoff);
            cp16(base + ARRB + d, Bh + boff);
        }
        CP_COMMIT();
    };

    stage(0, 0);

    for (int it = 0; it < nKiter; it++) {
        CP_WAIT(0);
        __syncthreads();     // publishes staged data; also guards buffer reuse
        if (it + 1 < nKiter)
            stage((it + 1) & 1, (it + 1) * BK);   // overlaps compute below

        const uint32_t base = sb0 + (it & 1) * STAGEB;
        const uint32_t aAh = base + offA;
        const uint32_t aBh = base + ARRB + offB;

        #pragma unroll
        for (int s = 0; s < 2; s++) {
            unsigned bh[4][2];
            ldsm4(bh[0][0], bh[0][1], bh[1][0], bh[1][1], aBh + s * 32);
            ldsm4(bh[2][0], bh[2][1], bh[3][0], bh[3][1], aBh + 16 * BKP * 2 + s * 32);
            #pragma unroll
            for (int mi = 0; mi < 4; mi++) {
                unsigned ah0, ah1, ah2, ah3;
                ldsm4(ah0, ah1, ah2, ah3, aAh + mi * (16 * BKP * 2) + s * 32);
                #pragma unroll
                for (int ni = 0; ni < 4; ni++)
                    mma_f16(acc[mi][ni], ah0, ah1, ah2, ah3, bh[ni][0], bh[ni][1]);
            }
        }
    }

    const int region = col0 >> 8;     // for EPI_QKV: 0=q, 1=k, 2=v
    #pragma unroll
    for (int mi = 0; mi < 4; mi++) {
        int r = row0 + warp_m * 64 + mi * 16 + g;
        #pragma unroll
        for (int ni = 0; ni < 4; ni++) {
            int c = col0 + warp_n * 32 + ni * 8 + 2 * t;
            float bx = bias[c], by = bias[c + 1];
            float4 d = acc[mi][ni];
            float v0 = d.x + bx, v1 = d.y + by;
            float v2 = d.z + bx, v3 = d.w + by;
            if (epi == EPI_QKV) {
                int local = c & 255;
                if (region == 0) {
                    if (r < M) {
                        g_q[(size_t)r * CC + local]     = v0 * QK_SCALE;
                        g_q[(size_t)r * CC + local + 1] = v1 * QK_SCALE;
                    }
                    if (r + 8 < M) {
                        g_q[(size_t)(r + 8) * CC + local]     = v2 * QK_SCALE;
                        g_q[(size_t)(r + 8) * CC + local + 1] = v3 * QK_SCALE;
                    }
                } else {
                    int h  = local >> 5;
                    int dd = (local & 31) + (region == 2 ? 32 : 0);
                    if (r < M) {
                        __half2 p; p.x = __float2half_rn(v0); p.y = __float2half_rn(v1);
                        *(__half2*)&g_kv[((size_t)r * HH + h) * 64 + dd] = p;
                    }
                    if (r + 8 < M) {
                        __half2 p; p.x = __float2half_rn(v2); p.y = __float2half_rn(v3);
                        *(__half2*)&g_kv[((size_t)(r + 8) * HH + h) * 64 + dd] = p;
                    }
                }
            } else if (epi == EPI_GELU) {
                v0 = fast_gelu(v0);
                v1 = fast_gelu(v1);
                v2 = fast_gelu(v2);
                v3 = fast_gelu(v3);
                if (r < M) {
                    size_t o = (size_t)r * Nn + c;
                    __half2 p; p.x = __float2half_rn(v0); p.y = __float2half_rn(v1);
                    *(__half2*)&Ch[o] = p;
                }
                if (r + 8 < M) {
                    size_t o = (size_t)(r + 8) * Nn + c;
                    __half2 p; p.x = __float2half_rn(v2); p.y = __float2half_rn(v3);
                    *(__half2*)&Ch[o] = p;
                }
            } else {
                if (r < M) {
                    size_t o = (size_t)r * Nn + c;
                    float r0 = resid[o], r1 = resid[o + 1];
                    Cf[o] = v0 + r0; Cf[o + 1] = v1 + r1;
                }
                if (r + 8 < M) {
                    size_t o = (size_t)(r + 8) * Nn + c;
                    float r2 = resid[o], r3 = resid[o + 1];
                    Cf[o] = v2 + r2; Cf[o + 1] = v3 + r3;
                }
            }
        }
    }
}

// ---------------- Edge-softmax attention -------------------------------------
// block per node; double-buffered 16-edge smem chunks; paired-edge reduce.
#define ACH 16
__global__ __launch_bounds__(256)
void attn_kernel(__half* __restrict__ oh)
{
    __shared__ __align__(16) __half skv[2 * ACH * 512];
    int n    = blockIdx.x;
    int tid  = threadIdx.x;
    int h    = tid >> 5;
    int lane = tid & 31;
    float2 q2 = *(const float2*)&g_q[(size_t)n * CC + h * HDIM + 2 * (lane & 15)];
    int s = g_rowptr[n];
    int e = g_rowptr[n + 1];
    float m = -INFINITY, l = 0.0f;
    float accv = 0.0f;                         // v accumulation, dim = lane
    const uint32_t sbase = smem_u32(skv);
    const bool lo = (lane < 16);
    const int nch = (e - s + ACH - 1) / ACH;

    auto stage = [&](int c) {
        int c0  = s + c * ACH;
        int cnt = min(ACH, e - c0);
        uint32_t dst0 = sbase + (uint32_t)((c & 1) * ACH * 1024);
        for (int idx = tid; idx < cnt * 64; idx += 256) {
            int ed  = idx >> 6;
            int c16 = idx & 63;
            const char* src = (const char*)(g_kv + (size_t)g_nbr[c0 + ed] * 512)
                              + c16 * 16;
            cp16(dst0 + (uint32_t)(ed * 1024 + c16 * 16), src);
        }
        CP_COMMIT();
    };

    if (nch > 0) stage(0);

    for (int c = 0; c < nch; c++) {
        CP_WAIT(0);
        __syncthreads();                       // publishes chunk c; guards reuse
        if (c + 1 < nch) stage(c + 1);

        const __half*  buf  = skv + (c & 1) * ACH * 512;
        const __half2* buf2 = (const __half2*)buf;
        int cnt = min(ACH, e - (s + c * ACH));

        int u = 0;
        for (; u + 3 < cnt; u += 4) {
            float part[2];
            #pragma unroll
            for (int p = 0; p < 2; p++) {
                int ed = u + 2 * p + (lo ? 0 : 1);
                __half2 kh = buf2[ed * 256 + h * 32 + (lane & 15)];
                float2 kf = __half22float2(kh);
                part[p] = q2.x * kf.x + q2.y * kf.y;
            }
            #pragma unroll
            for (int o = 8; o; o >>= 1) {
                part[0] += __shfl_xor_sync(0xffffffffu, part[0], o);
                part[1] += __shfl_xor_sync(0xffffffffu, part[1], o);
            }
            float oth0 = __shfl_xor_sync(0xffffffffu, part[0], 16);
            float oth1 = __shfl_xor_sync(0xffffffffu, part[1], 16);
            float d0 = lo ? part[0] : oth0;
            float d1 = lo ? oth0 : part[0];
            float d2 = lo ? part[1] : oth1;
            float d3 = lo ? oth1 : part[1];
            float mb = fmaxf(fmaxf(d0, d1), fmaxf(d2, d3));
            float mn = fmaxf(m, mb);
            float sc = __expf(m - mn);
            float p0 = __expf(d0 - mn);
            float p1 = __expf(d1 - mn);
            float p2 = __expf(d2 - mn);
            float p3 = __expf(d3 - mn);
            l = l * sc + (p0 + p1 + p2 + p3);
            float v0 = __half2float(buf[(u    ) * 512 + h * 64 + 32 + lane]);
            float v1 = __half2float(buf[(u + 1) * 512 + h * 64 + 32 + lane]);
            float v2 = __half2float(buf[(u + 2) * 512 + h * 64 + 32 + lane]);
            float v3 = __half2float(buf[(u + 3) * 512 + h * 64 + 32 + lane]);
            accv = accv * sc + p0 * v0 + p1 * v1 + p2 * v2 + p3 * v3;
            m = mn;
        }
        for (; u < cnt; u++) {
            __half2 kh = buf2[u * 256 + h * 32 + (lane & 15)];
            float2 kf = __half22float2(kh);
            float d = lo ? (q2.x * kf.x + q2.y * kf.y) : 0.0f;
            #pragma unroll
            for (int o = 16; o; o >>= 1) d += __shfl_xor_sync(0xffffffffu, d, o);
            float mn = fmaxf(m, d);
            float sc = __expf(m - mn);
            float p  = __expf(d - mn);
            l = l * sc + p;
            float vv = __half2float(buf[u * 512 + h * 64 + 32 + lane]);
            accv = accv * sc + p * vv;
            m = mn;
        }
    }
    float inv = (l > 0.0f) ? (1.0f / l) : 0.0f;
    oh[(size_t)n * CC + h * HDIM + lane] = __float2half_rn(accv * inv);
}

// ---------------- host launcher ---------------------------------------------
extern "C" void kernel_launch(void* const* d_in, const int* in_sizes, int n_in,
                              void* d_out, int out_size)
{
    const float* feats  = (const float*)d_in[0];
    const int*   ei     = (const int*)d_in[2];
    const float* ln1_g  = (const float*)d_in[3];
    const float* ln1_b  = (const float*)d_in[4];
    const float* qkv_w  = (const float*)d_in[5];
    const float* qkv_b  = (const float*)d_in[6];
    const float* proj_w = (const float*)d_in[7];
    const float* proj_b = (const float*)d_in[8];
    const float* ln2_g  = (const float*)d_in[9];
    const float* ln2_b  = (const float*)d_in[10];
    const float* fc1_w  = (const float*)d_in[11];
    const float* fc1_b  = (const float*)d_in[12];
    const float* fc2_w  = (const float*)d_in[13];
    const float* fc2_b  = (const float*)d_in[14];
    float* out = (float*)d_out;

    float *p_f2;
    cudaGetSymbolAddress((void**)&p_f2,  g_f2);
    __half *p_xn_h, *p_at_h, *p_y_h, *p_h1_h;
    cudaGetSymbolAddress((void**)&p_xn_h, g_xn_h);
    cudaGetSymbolAddress((void**)&p_at_h, g_at_h);
    cudaGetSymbolAddress((void**)&p_y_h,  g_y_h);
    cudaGetSymbolAddress((void**)&p_h1_h, g_h1_h);
    __half *p_wqkv, *p_wprj, *p_wfc1, *p_wfc2;
    cudaGetSymbolAddress((void**)&p_wqkv, g_wqkv);
    cudaGetSymbolAddress((void**)&p_wprj, g_wprj);
    cudaGetSymbolAddress((void**)&p_wfc1, g_wfc1);
    cudaGetSymbolAddress((void**)&p_wfc2, g_wfc2);
    int* p_cnt;
    cudaGetSymbolAddress((void**)&p_cnt, g_cnt);

    const int SMEM_BYTES = 2 * STAGEB;   // 40960 -> 2 CTAs/SM
    static int init_done = 0;
    static cudaStream_t sB;
    static cudaEvent_t evFork, evW, evJoin;
    if (!init_done) {
        cudaFuncSetAttribute(gemm_sp_kernel,
                             cudaFuncAttributeMaxDynamicSharedMemorySize, SMEM_BYTES);
        cudaStreamCreateWithFlags(&sB, cudaStreamNonBlocking);
        cudaEventCreateWithFlags(&evFork, cudaEventDisableTiming);
        cudaEventCreateWithFlags(&evW,    cudaEventDisableTiming);
        cudaEventCreateWithFlags(&evJoin, cudaEventDisableTiming);
        init_done = 1;
    }

    const int nscan = (NN + SCAN_B - 1) / SCAN_B;
    const int MROWS = (NN + BM - 1) / BM;

    // fork side stream
    cudaEventRecord(evFork, 0);
    cudaStreamWaitEvent(sB, evFork, 0);

    // ---- stream B: qkv weight round first (overlaps LN1), then CSR + rounds
    round_kernel<<<(3*CC*CC + 255)/256, 256, 0, sB>>>(qkv_w, p_wqkv, 3*CC*CC);
    cudaEventRecord(evW, sB);
    cudaMemsetAsync(p_cnt, 0, NN * sizeof(int), sB);
    count_kernel<<<(MM + 255) / 256, 256, 0, sB>>>(ei);
    scan1_kernel<<<nscan, SCAN_B, 0, sB>>>();
    scan2_kernel<<<1, 128, 0, sB>>>(nscan);
    scan3_kernel<<<nscan, SCAN_B, 0, sB>>>();
    scatter_kernel<<<(MM + 255) / 256, 256, 0, sB>>>(ei);
    round_kernel<<<(CC*CC   + 255)/256, 256, 0, sB>>>(proj_w, p_wprj, CC*CC);
    round_kernel<<<(HIDN*CC + 255)/256, 256, 0, sB>>>(fc1_w, p_wfc1, HIDN*CC);
    round_kernel<<<(CC*HIDN + 255)/256, 256, 0, sB>>>(fc2_w, p_wfc2, CC*HIDN);
    cudaEventRecord(evJoin, sB);

    // ---- main stream
    ln_kernel<<<(NN + 7) / 8, 256>>>(feats, ln1_g, ln1_b, p_xn_h);
    cudaStreamWaitEvent(0, evW, 0);     // need qkv weights

    // qkv (1-term everywhere)
    {
        dim3 grid(768 / BN, MROWS);
        gemm_sp_kernel<<<grid, 256, SMEM_BYTES>>>(p_xn_h, p_wqkv,
                                                  qkv_b, nullptr, nullptr, nullptr,
                                                  NN, 768, CC, EPI_QKV);
    }

    // join: attention needs CSR; later GEMMs need rounded weights
    cudaStreamWaitEvent(0, evJoin, 0);

    attn_kernel<<<NN, 256>>>(p_at_h);

    // proj
    {
        dim3 grid(CC / BN, MROWS);
        gemm_sp_kernel<<<grid, 256, SMEM_BYTES>>>(p_at_h, p_wprj,
                                                  proj_b, feats, p_f2, nullptr,
                                                  NN, CC, CC, EPI_RES);
    }

    // LN2 -> fp16
    ln_kernel<<<(NN + 7) / 8, 256>>>(p_f2, ln2_g, ln2_b, p_y_h);

    // fc1 + gelu
    {
        dim3 grid(HIDN / BN, MROWS);
        gemm_sp_kernel<<<grid, 256, SMEM_BYTES>>>(p_y_h, p_wfc1,
                                                  fc1_b, nullptr, nullptr, p_h1_h,
                                                  NN, HIDN, CC, EPI_GELU);
    }

    // fc2 + residual
    {
        dim3 grid(CC / BN, MROWS);
        gemm_sp_kernel<<<grid, 256, SMEM_BYTES>>>(p_h1_h, p_wfc2,
                                                  fc2_b, p_f2, out, nullptr,
                                                  NN, CC, HIDN, EPI_RES);
    }
}